// round 1
// baseline (speedup 1.0000x reference)
#include <cuda_runtime.h>
#include <cuda_bf16.h>
#include <cstdint>

// Problem constants
#define BB 4
#define SS 2048
#define DD 1024
#define HH 16
#define HD 64
#define BS (BB*SS)          // 8192

// Scratch (device globals; no allocation allowed)
__device__ float g_Q[BS*DD];     // [b, s, h*HD] natural layout, pre-scaled by 1/sqrt(HD)
__device__ float g_K[BS*DD];
__device__ float g_V[BS*DD];
__device__ float g_ctx[BS*DD];   // [b, s, d]

// ---------------------------------------------------------------------------
// GEMM: C[M,N] = A[M,K] * W[N,K]^T   (both row-major, NT)
// 128x128x16 tile, 256 threads, 8x8 per thread.
// ---------------------------------------------------------------------------

__global__ __launch_bounds__(256)
void qkv_kernel(const float* __restrict__ x,
                const float* __restrict__ wq,
                const float* __restrict__ wk,
                const float* __restrict__ wv)
{
    __shared__ float As[16][128];
    __shared__ float Bs[16][128];

    const int z = blockIdx.z;
    const float* __restrict__ W = (z == 0) ? wq : (z == 1) ? wk : wv;
    float* __restrict__ O = (z == 0) ? g_Q : (z == 1) ? g_K : g_V;
    const float scale = (z == 0) ? 0.125f : 1.0f;   // 1/sqrt(HD) folded into Q

    const int m0 = blockIdx.x * 128;
    const int n0 = blockIdx.y * 128;
    const int tid = threadIdx.x;
    const int tx = tid & 15;
    const int ty = tid >> 4;

    float acc[8][8];
    #pragma unroll
    for (int i = 0; i < 8; i++)
        #pragma unroll
        for (int j = 0; j < 8; j++) acc[i][j] = 0.f;

    for (int k0 = 0; k0 < DD; k0 += 16) {
        #pragma unroll
        for (int it = 0; it < 2; it++) {
            int idx = tid + it * 256;          // 0..511
            int row = idx >> 2;                // 0..127
            int kq  = (idx & 3) * 4;           // 0,4,8,12
            float4 va = *(const float4*)&x[(size_t)(m0 + row) * DD + k0 + kq];
            As[kq + 0][row] = va.x; As[kq + 1][row] = va.y;
            As[kq + 2][row] = va.z; As[kq + 3][row] = va.w;
            float4 vb = *(const float4*)&W[(size_t)(n0 + row) * DD + k0 + kq];
            Bs[kq + 0][row] = vb.x; Bs[kq + 1][row] = vb.y;
            Bs[kq + 2][row] = vb.z; Bs[kq + 3][row] = vb.w;
        }
        __syncthreads();

        #pragma unroll
        for (int kk = 0; kk < 16; kk++) {
            float4 a0 = *(float4*)&As[kk][ty * 8];
            float4 a1 = *(float4*)&As[kk][ty * 8 + 4];
            float4 b0 = *(float4*)&Bs[kk][tx * 8];
            float4 b1 = *(float4*)&Bs[kk][tx * 8 + 4];
            float a[8] = {a0.x, a0.y, a0.z, a0.w, a1.x, a1.y, a1.z, a1.w};
            float b[8] = {b0.x, b0.y, b0.z, b0.w, b1.x, b1.y, b1.z, b1.w};
            #pragma unroll
            for (int i = 0; i < 8; i++)
                #pragma unroll
                for (int j = 0; j < 8; j++)
                    acc[i][j] = fmaf(a[i], b[j], acc[i][j]);
        }
        __syncthreads();
    }

    #pragma unroll
    for (int i = 0; i < 8; i++) {
        int m = m0 + ty * 8 + i;
        #pragma unroll
        for (int j = 0; j < 8; j++) {
            int n = n0 + tx * 8 + j;
            O[(size_t)m * DD + n] = acc[i][j] * scale;
        }
    }
}

__global__ __launch_bounds__(256)
void oproj_kernel(const float* __restrict__ wo,
                  const float* __restrict__ wo_b,
                  float* __restrict__ out)
{
    __shared__ float As[16][128];
    __shared__ float Bs[16][128];

    const int m0 = blockIdx.x * 128;
    const int n0 = blockIdx.y * 128;
    const int tid = threadIdx.x;
    const int tx = tid & 15;
    const int ty = tid >> 4;

    float acc[8][8];
    #pragma unroll
    for (int i = 0; i < 8; i++)
        #pragma unroll
        for (int j = 0; j < 8; j++) acc[i][j] = 0.f;

    for (int k0 = 0; k0 < DD; k0 += 16) {
        #pragma unroll
        for (int it = 0; it < 2; it++) {
            int idx = tid + it * 256;
            int row = idx >> 2;
            int kq  = (idx & 3) * 4;
            float4 va = *(const float4*)&g_ctx[(size_t)(m0 + row) * DD + k0 + kq];
            As[kq + 0][row] = va.x; As[kq + 1][row] = va.y;
            As[kq + 2][row] = va.z; As[kq + 3][row] = va.w;
            float4 vb = *(const float4*)&wo[(size_t)(n0 + row) * DD + k0 + kq];
            Bs[kq + 0][row] = vb.x; Bs[kq + 1][row] = vb.y;
            Bs[kq + 2][row] = vb.z; Bs[kq + 3][row] = vb.w;
        }
        __syncthreads();

        #pragma unroll
        for (int kk = 0; kk < 16; kk++) {
            float4 a0 = *(float4*)&As[kk][ty * 8];
            float4 a1 = *(float4*)&As[kk][ty * 8 + 4];
            float4 b0 = *(float4*)&Bs[kk][tx * 8];
            float4 b1 = *(float4*)&Bs[kk][tx * 8 + 4];
            float a[8] = {a0.x, a0.y, a0.z, a0.w, a1.x, a1.y, a1.z, a1.w};
            float b[8] = {b0.x, b0.y, b0.z, b0.w, b1.x, b1.y, b1.z, b1.w};
            #pragma unroll
            for (int i = 0; i < 8; i++)
                #pragma unroll
                for (int j = 0; j < 8; j++)
                    acc[i][j] = fmaf(a[i], b[j], acc[i][j]);
        }
        __syncthreads();
    }

    #pragma unroll
    for (int i = 0; i < 8; i++) {
        int m = m0 + ty * 8 + i;
        #pragma unroll
        for (int j = 0; j < 8; j++) {
            int n = n0 + tx * 8 + j;
            out[(size_t)m * DD + n] = acc[i][j] + wo_b[n];
        }
    }
}

// ---------------------------------------------------------------------------
// Flash attention (causal), fp32. One CTA per (q-tile, b*h). Br=Bc=64.
// 256 threads (16x16), each owns a 4x4 micro-tile.
// ---------------------------------------------------------------------------

#define FSTR 68   // padded smem stride (floats): 16B-aligned float4, low conflicts

__global__ __launch_bounds__(256)
void flash_kernel()
{
    extern __shared__ float sm[];
    float* QsT  = sm;                  // [64 d][64 q]  stride FSTR
    float* KsT  = sm + 64 * FSTR;      // [64 d][64 k]
    float* Vs   = sm + 2 * 64 * FSTR;  // [64 k][64 hd]
    float* PsT  = sm + 3 * 64 * FSTR;  // [64 k][64 q]
    float* mrow = sm + 4 * 64 * FSTR;  // [64]
    float* lrow = mrow + 64;
    float* arow = lrow + 64;

    const int itile = blockIdx.x;          // q tile 0..31
    const int bh    = blockIdx.y;          // 0..63
    const int b = bh >> 4, h = bh & 15;

    const size_t base = (size_t)b * SS * DD + (size_t)h * HD;
    const float* __restrict__ Qp = g_Q + base;
    const float* __restrict__ Kp = g_K + base;
    const float* __restrict__ Vp = g_V + base;

    const int tid = threadIdx.x;
    const int tx = tid & 15;
    const int ty = tid >> 4;

    // Load Q tile transposed: QsT[d][q]
    #pragma unroll
    for (int i = 0; i < 4; i++) {
        int idx = tid + i * 256;           // 0..1023
        int row = idx >> 4;                // 0..63 (q within tile)
        int c4  = (idx & 15) * 4;          // d
        float4 v = *(const float4*)&Qp[(size_t)(itile * 64 + row) * DD + c4];
        QsT[(c4 + 0) * FSTR + row] = v.x;
        QsT[(c4 + 1) * FSTR + row] = v.y;
        QsT[(c4 + 2) * FSTR + row] = v.z;
        QsT[(c4 + 3) * FSTR + row] = v.w;
    }
    if (tid < 64) { mrow[tid] = -1e30f; lrow[tid] = 0.f; }

    float acc[4][4];
    #pragma unroll
    for (int i = 0; i < 4; i++)
        #pragma unroll
        for (int j = 0; j < 4; j++) acc[i][j] = 0.f;

    __syncthreads();

    for (int kt = 0; kt <= itile; kt++) {
        // Load K (transposed) and V (natural)
        #pragma unroll
        for (int i = 0; i < 4; i++) {
            int idx = tid + i * 256;
            int row = idx >> 4;
            int c4  = (idx & 15) * 4;
            float4 kv = *(const float4*)&Kp[(size_t)(kt * 64 + row) * DD + c4];
            KsT[(c4 + 0) * FSTR + row] = kv.x;
            KsT[(c4 + 1) * FSTR + row] = kv.y;
            KsT[(c4 + 2) * FSTR + row] = kv.z;
            KsT[(c4 + 3) * FSTR + row] = kv.w;
            float4 vv = *(const float4*)&Vp[(size_t)(kt * 64 + row) * DD + c4];
            *(float4*)&Vs[row * FSTR + c4] = vv;
        }
        __syncthreads();

        // S = Q K^T  (4x4 per thread)
        float s[4][4];
        #pragma unroll
        for (int i = 0; i < 4; i++)
            #pragma unroll
            for (int j = 0; j < 4; j++) s[i][j] = 0.f;

        #pragma unroll 8
        for (int d = 0; d < 64; d++) {
            float4 aq = *(float4*)&QsT[d * FSTR + ty * 4];
            float4 bk = *(float4*)&KsT[d * FSTR + tx * 4];
            float a[4] = {aq.x, aq.y, aq.z, aq.w};
            float bb[4] = {bk.x, bk.y, bk.z, bk.w};
            #pragma unroll
            for (int i = 0; i < 4; i++)
                #pragma unroll
                for (int j = 0; j < 4; j++)
                    s[i][j] = fmaf(a[i], bb[j], s[i][j]);
        }

        if (kt == itile) {   // causal mask on diagonal tile only
            #pragma unroll
            for (int i = 0; i < 4; i++)
                #pragma unroll
                for (int j = 0; j < 4; j++)
                    if (tx * 4 + j > ty * 4 + i) s[i][j] = -1e30f;
        }

        // Store S transposed: PsT[k][q]
        #pragma unroll
        for (int i = 0; i < 4; i++)
            #pragma unroll
            for (int j = 0; j < 4; j++)
                PsT[(tx * 4 + j) * FSTR + (ty * 4 + i)] = s[i][j];
        __syncthreads();

        // Online softmax per q-row (threads 0..63, q = tid)
        if (tid < 64) {
            float mo = mrow[tid];
            float mx = mo;
            #pragma unroll 8
            for (int k2 = 0; k2 < 64; k2++)
                mx = fmaxf(mx, PsT[k2 * FSTR + tid]);
            float sum = 0.f;
            #pragma unroll 8
            for (int k2 = 0; k2 < 64; k2++) {
                float e = __expf(PsT[k2 * FSTR + tid] - mx);
                PsT[k2 * FSTR + tid] = e;
                sum += e;
            }
            float al = __expf(mo - mx);
            lrow[tid] = lrow[tid] * al + sum;
            mrow[tid] = mx;
            arow[tid] = al;
        }
        __syncthreads();

        // Rescale accumulators, then ctx += P * V
        float al4[4];
        #pragma unroll
        for (int i = 0; i < 4; i++) al4[i] = arow[ty * 4 + i];
        #pragma unroll
        for (int i = 0; i < 4; i++)
            #pragma unroll
            for (int j = 0; j < 4; j++) acc[i][j] *= al4[i];

        #pragma unroll 8
        for (int k2 = 0; k2 < 64; k2++) {
            float4 pv = *(float4*)&PsT[k2 * FSTR + ty * 4];
            float4 vv = *(float4*)&Vs[k2 * FSTR + tx * 4];
            float p[4] = {pv.x, pv.y, pv.z, pv.w};
            float v[4] = {vv.x, vv.y, vv.z, vv.w};
            #pragma unroll
            for (int i = 0; i < 4; i++)
                #pragma unroll
                for (int j = 0; j < 4; j++)
                    acc[i][j] = fmaf(p[i], v[j], acc[i][j]);
        }
        __syncthreads();   // protect KsT/Vs/PsT before next iteration's loads
    }

    // Normalize and write ctx in [b, s, h*HD+hd] layout
    #pragma unroll
    for (int i = 0; i < 4; i++) {
        float inv = 1.0f / lrow[ty * 4 + i];
        int sg = itile * 64 + ty * 4 + i;
        #pragma unroll
        for (int j = 0; j < 4; j++) {
            g_ctx[((size_t)(b * SS + sg)) * DD + h * HD + tx * 4 + j] = acc[i][j] * inv;
        }
    }
}

// ---------------------------------------------------------------------------

extern "C" void kernel_launch(void* const* d_in, const int* in_sizes, int n_in,
                              void* d_out, int out_size)
{
    const float* x    = (const float*)d_in[0];
    const float* wq   = (const float*)d_in[1];
    const float* wk   = (const float*)d_in[2];
    const float* wv   = (const float*)d_in[3];
    const float* wo   = (const float*)d_in[4];
    const float* wo_b = (const float*)d_in[5];
    float* out = (float*)d_out;

    const int flash_smem = (4 * 64 * FSTR + 3 * 64) * sizeof(float);  // ~70.4 KB
    cudaFuncSetAttribute(flash_kernel, cudaFuncAttributeMaxDynamicSharedMemorySize,
                         flash_smem);

    // 1. QKV projections (z selects weight/output)
    qkv_kernel<<<dim3(BS / 128, DD / 128, 3), 256>>>(x, wq, wk, wv);

    // 2. Causal flash attention
    flash_kernel<<<dim3(SS / 64, BB * HH), 256, flash_smem>>>();

    // 3. Output projection + bias
    oproj_kernel<<<dim3(BS / 128, DD / 128), 256>>>(wo, wo_b, out);
}

// round 3
// speedup vs baseline: 1.5135x; 1.5135x over previous
#include <cuda_runtime.h>
#include <cuda_bf16.h>
#include <cstdint>

// Problem constants
#define BB 4
#define SS 2048
#define DD 1024
#define HH 16
#define HD 64
#define BS (BB*SS)          // 8192

// ---------------------------------------------------------------------------
// Scratch (device globals; no allocation allowed)
// ---------------------------------------------------------------------------
__device__ float g_Q[BS*DD];     // pre-scaled by 1/sqrt(HD)
__device__ float g_K[BS*DD];
__device__ float g_V[BS*DD];
__device__ float g_ctx[BS*DD];

__device__ __nv_bfloat16 g_xh[BS*DD], g_xl[BS*DD];
__device__ __nv_bfloat16 g_wh[3*DD*DD], g_wl[3*DD*DD];      // fused Wq|Wk|Wv rows
__device__ __nv_bfloat16 g_woh[DD*DD], g_wol[DD*DD];
__device__ __nv_bfloat16 g_ch[BS*DD], g_cl[BS*DD];

// ---------------------------------------------------------------------------
// Portable (compute_103-safe) PTX helpers: cp.async / ldmatrix / mma.sync
// ---------------------------------------------------------------------------
__device__ __forceinline__ uint32_t smem_u32(const void* p) {
    uint32_t a;
    asm("{ .reg .u64 t; cvta.to.shared.u64 t, %1; cvt.u32.u64 %0, t; }" : "=r"(a) : "l"(p));
    return a;
}
__device__ __forceinline__ void cp16(uint32_t dst, const void* src) {
    asm volatile("cp.async.cg.shared.global [%0], [%1], 16;" :: "r"(dst), "l"(src) : "memory");
}
#define CP_COMMIT() asm volatile("cp.async.commit_group;" ::: "memory")
#define CP_WAIT1()  asm volatile("cp.async.wait_group 1;" ::: "memory")
#define CP_WAIT0()  asm volatile("cp.async.wait_group 0;" ::: "memory")

__device__ __forceinline__ void ldsm4(uint32_t& r0, uint32_t& r1, uint32_t& r2, uint32_t& r3,
                                      uint32_t addr) {
    asm volatile("ldmatrix.sync.aligned.m8n8.x4.shared.b16 {%0,%1,%2,%3}, [%4];"
                 : "=r"(r0), "=r"(r1), "=r"(r2), "=r"(r3) : "r"(addr));
}
__device__ __forceinline__ void mma16816(float* c,
                                         uint32_t a0, uint32_t a1, uint32_t a2, uint32_t a3,
                                         uint32_t b0, uint32_t b1) {
    asm volatile("mma.sync.aligned.m16n8k16.row.col.f32.bf16.bf16.f32 "
                 "{%0,%1,%2,%3}, {%4,%5,%6,%7}, {%8,%9}, {%0,%1,%2,%3};"
                 : "+f"(c[0]), "+f"(c[1]), "+f"(c[2]), "+f"(c[3])
                 : "r"(a0), "r"(a1), "r"(a2), "r"(a3), "r"(b0), "r"(b1));
}

// ---------------------------------------------------------------------------
// Split fp32 -> (bf16 hi, bf16 lo)
// ---------------------------------------------------------------------------
__global__ __launch_bounds__(256)
void split_kernel(const float* __restrict__ src, __nv_bfloat16* __restrict__ hi,
                  __nv_bfloat16* __restrict__ lo, int n4)
{
    int i = blockIdx.x * 256 + threadIdx.x;
    if (i >= n4) return;
    float4 v = ((const float4*)src)[i];
    __nv_bfloat16 h0 = __float2bfloat16(v.x), h1 = __float2bfloat16(v.y),
                  h2 = __float2bfloat16(v.z), h3 = __float2bfloat16(v.w);
    __nv_bfloat162 hp0 = {h0, h1}, hp1 = {h2, h3};
    __nv_bfloat162 lp0 = {__float2bfloat16(v.x - __bfloat162float(h0)),
                          __float2bfloat16(v.y - __bfloat162float(h1))};
    __nv_bfloat162 lp1 = {__float2bfloat16(v.z - __bfloat162float(h2)),
                          __float2bfloat16(v.w - __bfloat162float(h3))};
    ((__nv_bfloat162*)hi)[i*2+0] = hp0;  ((__nv_bfloat162*)hi)[i*2+1] = hp1;
    ((__nv_bfloat162*)lo)[i*2+0] = lp0;  ((__nv_bfloat162*)lo)[i*2+1] = lp1;
}

// ---------------------------------------------------------------------------
// bf16x3 GEMM via mma.sync:  C[M, Ntot] = A*B^T, 3 K-passes (Ah·Bh, Al·Bh, Ah·Bl)
// CTA 128x128, BK=32 double-buffered cp.async, 8 warps (2M x 4N), warp 64x32.
// mode 0: write g_Q/g_K/g_V (Ntot=3072, Q scaled 0.125); mode 1: out + bias.
// ---------------------------------------------------------------------------
#define GM_BM 128
#define GM_BN 128
#define GM_BK 32
#define GM_TILES 96            // 3 passes * (1024/32)
#define LSTR 40                // smem row stride in bf16 (80B): conflict-free ldmatrix

__global__ __launch_bounds__(256)
void gemm_mma_kernel(const __nv_bfloat16* __restrict__ Ah,
                     const __nv_bfloat16* __restrict__ Al,
                     const __nv_bfloat16* __restrict__ Bh,
                     const __nv_bfloat16* __restrict__ Bl,
                     float* __restrict__ outp,
                     const float* __restrict__ bias,
                     int mode)
{
    __shared__ __align__(16) __nv_bfloat16 As[2][GM_BM * LSTR];
    __shared__ __align__(16) __nv_bfloat16 Bs[2][GM_BN * LSTR];

    const int tid = threadIdx.x;
    const int lid = tid & 31;
    const int wid = tid >> 5;
    const int wm = wid >> 2;      // 0..1
    const int wn = wid & 3;       // 0..3

    const int m0 = blockIdx.x * GM_BM;
    const int n0 = blockIdx.y * GM_BN;

    const uint32_t aS = smem_u32(As);
    const uint32_t bS = smem_u32(Bs);
    const uint32_t ABUF = GM_BM * LSTR * 2;   // bytes per A buffer
    const uint32_t BBUF = GM_BN * LSTR * 2;

    float acc[4][4][4];
    #pragma unroll
    for (int i = 0; i < 4; i++)
        #pragma unroll
        for (int j = 0; j < 4; j++)
            #pragma unroll
            for (int c = 0; c < 4; c++) acc[i][j][c] = 0.f;

    auto load_tile = [&](int t) {
        const int pass = t >> 5;                  // 0,1,2
        const int k0 = (t & 31) * GM_BK;
        const __nv_bfloat16* Ap = (pass == 1) ? Al : Ah;
        const __nv_bfloat16* Bp = (pass == 2) ? Bl : Bh;
        const int buf = t & 1;
        #pragma unroll
        for (int it = 0; it < 2; it++) {
            int idx = tid + it * 256;             // 0..511
            int row = idx >> 2;                   // 0..127
            int ch  = idx & 3;                    // 16B chunk (8 bf16)
            cp16(aS + buf * ABUF + (uint32_t)(row * LSTR + ch * 8) * 2,
                 Ap + (size_t)(m0 + row) * DD + k0 + ch * 8);
            cp16(bS + buf * BBUF + (uint32_t)(row * LSTR + ch * 8) * 2,
                 Bp + (size_t)(n0 + row) * DD + k0 + ch * 8);
        }
        CP_COMMIT();
    };

    load_tile(0);
    load_tile(1);

    const int q = lid >> 3;            // ldmatrix quad
    const int r = lid & 7;
    const int arow = r + (q & 1) * 8;  // A: mat0 rows0-7 k0, mat1 rows8-15 k0, mat2 rows0-7 k8, mat3 rows8-15 k8
    const int acol = (q >> 1) * 8;
    const int brow = r + (q >> 1) * 8; // B: mat0 n0-7 k0, mat1 n0-7 k8, mat2 n8-15 k0, mat3 n8-15 k8
    const int bcol = (q & 1) * 8;

    for (int i = 0; i < GM_TILES; i++) {
        const int buf = i & 1;
        if (i + 1 < GM_TILES) { CP_WAIT1(); } else { CP_WAIT0(); }
        __syncthreads();

        #pragma unroll
        for (int kst = 0; kst < 2; kst++) {
            const int kb = kst * 16;
            uint32_t a[4][4];
            #pragma unroll
            for (int mt = 0; mt < 4; mt++) {
                uint32_t addr = aS + buf * ABUF +
                    (uint32_t)((wm * 64 + mt * 16 + arow) * LSTR + kb + acol) * 2;
                ldsm4(a[mt][0], a[mt][1], a[mt][2], a[mt][3], addr);
            }
            uint32_t b[4][2];
            #pragma unroll
            for (int np = 0; np < 2; np++) {
                uint32_t addr = bS + buf * BBUF +
                    (uint32_t)((wn * 32 + np * 16 + brow) * LSTR + kb + bcol) * 2;
                ldsm4(b[2*np][0], b[2*np][1], b[2*np+1][0], b[2*np+1][1], addr);
            }
            #pragma unroll
            for (int mt = 0; mt < 4; mt++)
                #pragma unroll
                for (int nt = 0; nt < 4; nt++)
                    mma16816(acc[mt][nt], a[mt][0], a[mt][1], a[mt][2], a[mt][3],
                             b[nt][0], b[nt][1]);
        }
        __syncthreads();
        if (i + 2 < GM_TILES) load_tile(i + 2);
    }

    // Epilogue
    if (mode == 0) {
        const int sel = n0 >> 10;
        float* __restrict__ OP = (sel == 0) ? g_Q : (sel == 1) ? g_K : g_V;
        const float scale = (sel == 0) ? 0.125f : 1.0f;
        const int ncta = n0 & (DD - 1);
        #pragma unroll
        for (int mt = 0; mt < 4; mt++) {
            int row = m0 + wm * 64 + mt * 16 + (lid >> 2);
            #pragma unroll
            for (int nt = 0; nt < 4; nt++) {
                int col = ncta + wn * 32 + nt * 8 + (lid & 3) * 2;
                float2 v0 = {acc[mt][nt][0] * scale, acc[mt][nt][1] * scale};
                float2 v1 = {acc[mt][nt][2] * scale, acc[mt][nt][3] * scale};
                *(float2*)&OP[(size_t)row * DD + col] = v0;
                *(float2*)&OP[(size_t)(row + 8) * DD + col] = v1;
            }
        }
    } else {
        #pragma unroll
        for (int mt = 0; mt < 4; mt++) {
            int row = m0 + wm * 64 + mt * 16 + (lid >> 2);
            #pragma unroll
            for (int nt = 0; nt < 4; nt++) {
                int col = n0 + wn * 32 + nt * 8 + (lid & 3) * 2;
                float2 bb = *(const float2*)&bias[col];
                float2 v0 = {acc[mt][nt][0] + bb.x, acc[mt][nt][1] + bb.y};
                float2 v1 = {acc[mt][nt][2] + bb.x, acc[mt][nt][3] + bb.y};
                *(float2*)&outp[(size_t)row * DD + col] = v0;
                *(float2*)&outp[(size_t)(row + 8) * DD + col] = v1;
            }
        }
    }
}

// ---------------------------------------------------------------------------
// Flash attention (causal), fp32 — unchanged
// ---------------------------------------------------------------------------
#define FSTR 68

__global__ __launch_bounds__(256)
void flash_kernel()
{
    extern __shared__ float smf[];
    float* QsT  = smf;
    float* KsT  = smf + 64 * FSTR;
    float* Vs   = smf + 2 * 64 * FSTR;
    float* PsT  = smf + 3 * 64 * FSTR;
    float* mrow = smf + 4 * 64 * FSTR;
    float* lrow = mrow + 64;
    float* arow = lrow + 64;

    const int itile = blockIdx.x;
    const int bh    = blockIdx.y;
    const int b = bh >> 4, h = bh & 15;

    const size_t base = (size_t)b * SS * DD + (size_t)h * HD;
    const float* __restrict__ Qp = g_Q + base;
    const float* __restrict__ Kp = g_K + base;
    const float* __restrict__ Vp = g_V + base;

    const int tid = threadIdx.x;
    const int tx = tid & 15;
    const int ty = tid >> 4;

    #pragma unroll
    for (int i = 0; i < 4; i++) {
        int idx = tid + i * 256;
        int row = idx >> 4;
        int c4  = (idx & 15) * 4;
        float4 v = *(const float4*)&Qp[(size_t)(itile * 64 + row) * DD + c4];
        QsT[(c4 + 0) * FSTR + row] = v.x;
        QsT[(c4 + 1) * FSTR + row] = v.y;
        QsT[(c4 + 2) * FSTR + row] = v.z;
        QsT[(c4 + 3) * FSTR + row] = v.w;
    }
    if (tid < 64) { mrow[tid] = -1e30f; lrow[tid] = 0.f; }

    float acc[4][4];
    #pragma unroll
    for (int i = 0; i < 4; i++)
        #pragma unroll
        for (int j = 0; j < 4; j++) acc[i][j] = 0.f;

    __syncthreads();

    for (int kt = 0; kt <= itile; kt++) {
        #pragma unroll
        for (int i = 0; i < 4; i++) {
            int idx = tid + i * 256;
            int row = idx >> 4;
            int c4  = (idx & 15) * 4;
            float4 kv = *(const float4*)&Kp[(size_t)(kt * 64 + row) * DD + c4];
            KsT[(c4 + 0) * FSTR + row] = kv.x;
            KsT[(c4 + 1) * FSTR + row] = kv.y;
            KsT[(c4 + 2) * FSTR + row] = kv.z;
            KsT[(c4 + 3) * FSTR + row] = kv.w;
            float4 vv = *(const float4*)&Vp[(size_t)(kt * 64 + row) * DD + c4];
            *(float4*)&Vs[row * FSTR + c4] = vv;
        }
        __syncthreads();

        float s[4][4];
        #pragma unroll
        for (int i = 0; i < 4; i++)
            #pragma unroll
            for (int j = 0; j < 4; j++) s[i][j] = 0.f;

        #pragma unroll 8
        for (int d = 0; d < 64; d++) {
            float4 aq = *(float4*)&QsT[d * FSTR + ty * 4];
            float4 bk = *(float4*)&KsT[d * FSTR + tx * 4];
            float a[4] = {aq.x, aq.y, aq.z, aq.w};
            float bb[4] = {bk.x, bk.y, bk.z, bk.w};
            #pragma unroll
            for (int i = 0; i < 4; i++)
                #pragma unroll
                for (int j = 0; j < 4; j++)
                    s[i][j] = fmaf(a[i], bb[j], s[i][j]);
        }

        if (kt == itile) {
            #pragma unroll
            for (int i = 0; i < 4; i++)
                #pragma unroll
                for (int j = 0; j < 4; j++)
                    if (tx * 4 + j > ty * 4 + i) s[i][j] = -1e30f;
        }

        #pragma unroll
        for (int i = 0; i < 4; i++)
            #pragma unroll
            for (int j = 0; j < 4; j++)
                PsT[(tx * 4 + j) * FSTR + (ty * 4 + i)] = s[i][j];
        __syncthreads();

        if (tid < 64) {
            float mo = mrow[tid];
            float mx = mo;
            #pragma unroll 8
            for (int k2 = 0; k2 < 64; k2++)
                mx = fmaxf(mx, PsT[k2 * FSTR + tid]);
            float sum = 0.f;
            #pragma unroll 8
            for (int k2 = 0; k2 < 64; k2++) {
                float e = __expf(PsT[k2 * FSTR + tid] - mx);
                PsT[k2 * FSTR + tid] = e;
                sum += e;
            }
            float al = __expf(mo - mx);
            lrow[tid] = lrow[tid] * al + sum;
            mrow[tid] = mx;
            arow[tid] = al;
        }
        __syncthreads();

        float al4[4];
        #pragma unroll
        for (int i = 0; i < 4; i++) al4[i] = arow[ty * 4 + i];
        #pragma unroll
        for (int i = 0; i < 4; i++)
            #pragma unroll
            for (int j = 0; j < 4; j++) acc[i][j] *= al4[i];

        #pragma unroll 8
        for (int k2 = 0; k2 < 64; k2++) {
            float4 pv = *(float4*)&PsT[k2 * FSTR + ty * 4];
            float4 vv = *(float4*)&Vs[k2 * FSTR + tx * 4];
            float p[4] = {pv.x, pv.y, pv.z, pv.w};
            float v[4] = {vv.x, vv.y, vv.z, vv.w};
            #pragma unroll
            for (int i = 0; i < 4; i++)
                #pragma unroll
                for (int j = 0; j < 4; j++)
                    acc[i][j] = fmaf(p[i], v[j], acc[i][j]);
        }
        __syncthreads();
    }

    #pragma unroll
    for (int i = 0; i < 4; i++) {
        float inv = 1.0f / lrow[ty * 4 + i];
        int sg = itile * 64 + ty * 4 + i;
        #pragma unroll
        for (int j = 0; j < 4; j++) {
            g_ctx[((size_t)(b * SS + sg)) * DD + h * HD + tx * 4 + j] = acc[i][j] * inv;
        }
    }
}

// ---------------------------------------------------------------------------

extern "C" void kernel_launch(void* const* d_in, const int* in_sizes, int n_in,
                              void* d_out, int out_size)
{
    const float* x    = (const float*)d_in[0];
    const float* wq   = (const float*)d_in[1];
    const float* wk   = (const float*)d_in[2];
    const float* wv   = (const float*)d_in[3];
    const float* wo   = (const float*)d_in[4];
    const float* wo_b = (const float*)d_in[5];
    float* out = (float*)d_out;

    static int attr_done = 0;
    if (!attr_done) {
        cudaFuncSetAttribute(flash_kernel,
                             cudaFuncAttributeMaxDynamicSharedMemorySize,
                             (4 * 64 * FSTR + 3 * 64) * sizeof(float));
        attr_done = 1;
    }

    __nv_bfloat16 *xh, *xl, *wh, *wl, *woh, *wol, *ch, *cl;
    cudaGetSymbolAddress((void**)&xh,  g_xh);
    cudaGetSymbolAddress((void**)&xl,  g_xl);
    cudaGetSymbolAddress((void**)&wh,  g_wh);
    cudaGetSymbolAddress((void**)&wl,  g_wl);
    cudaGetSymbolAddress((void**)&woh, g_woh);
    cudaGetSymbolAddress((void**)&wol, g_wol);
    cudaGetSymbolAddress((void**)&ch,  g_ch);
    cudaGetSymbolAddress((void**)&cl,  g_cl);
    float* ctxp; cudaGetSymbolAddress((void**)&ctxp, g_ctx);

    // 1. split inputs to bf16 hi/lo
    split_kernel<<<(BS*DD/4 + 255)/256, 256>>>(x, xh, xl, BS*DD/4);
    split_kernel<<<(DD*DD/4 + 255)/256, 256>>>(wq, wh,           wl,           DD*DD/4);
    split_kernel<<<(DD*DD/4 + 255)/256, 256>>>(wk, wh + DD*DD,   wl + DD*DD,   DD*DD/4);
    split_kernel<<<(DD*DD/4 + 255)/256, 256>>>(wv, wh + 2*DD*DD, wl + 2*DD*DD, DD*DD/4);
    split_kernel<<<(DD*DD/4 + 255)/256, 256>>>(wo, woh, wol, DD*DD/4);

    // 2. fused QKV projection on tensor cores (mma.sync bf16x3): [8192 x 3072]
    gemm_mma_kernel<<<dim3(BS/GM_BM, 3*DD/GM_BN), 256>>>(
        xh, xl, wh, wl, nullptr, nullptr, 0);

    // 3. causal flash attention (fp32)
    const int flash_smem = (4 * 64 * FSTR + 3 * 64) * sizeof(float);
    flash_kernel<<<dim3(SS/64, BB*HH), 256, flash_smem>>>();

    // 4. split ctx, output projection + bias
    split_kernel<<<(BS*DD/4 + 255)/256, 256>>>(ctxp, ch, cl, BS*DD/4);
    gemm_mma_kernel<<<dim3(BS/GM_BM, DD/GM_BN), 256>>>(
        ch, cl, woh, wol, out, wo_b, 1);
}

// round 4
// speedup vs baseline: 2.7064x; 1.7882x over previous
#include <cuda_runtime.h>
#include <cuda_bf16.h>
#include <cstdint>

// Problem constants
#define BB 4
#define SS 2048
#define DD 1024
#define HH 16
#define HD 64
#define BS (BB*SS)          // 8192

// ---------------------------------------------------------------------------
// Scratch (device globals; no allocation allowed)
// ---------------------------------------------------------------------------
__device__ __nv_bfloat16 g_xh[BS*DD], g_xl[BS*DD];
__device__ __nv_bfloat16 g_wh[3*DD*DD], g_wl[3*DD*DD];      // fused Wq|Wk|Wv rows
__device__ __nv_bfloat16 g_woh[DD*DD], g_wol[DD*DD];
__device__ __nv_bfloat16 g_qh[BS*DD], g_ql[BS*DD];          // Q (scaled) hi/lo
__device__ __nv_bfloat16 g_kh[BS*DD], g_kl[BS*DD];
__device__ __nv_bfloat16 g_vh[BS*DD], g_vl[BS*DD];
__device__ __nv_bfloat16 g_ch[BS*DD], g_cl[BS*DD];          // ctx hi/lo

// ---------------------------------------------------------------------------
// Portable (compute_103-safe) PTX helpers
// ---------------------------------------------------------------------------
__device__ __forceinline__ uint32_t smem_u32(const void* p) {
    uint32_t a;
    asm("{ .reg .u64 t; cvta.to.shared.u64 t, %1; cvt.u32.u64 %0, t; }" : "=r"(a) : "l"(p));
    return a;
}
__device__ __forceinline__ void cp16(uint32_t dst, const void* src) {
    asm volatile("cp.async.cg.shared.global [%0], [%1], 16;" :: "r"(dst), "l"(src) : "memory");
}
#define CP_COMMIT() asm volatile("cp.async.commit_group;" ::: "memory")
#define CP_WAIT0()  asm volatile("cp.async.wait_group 0;" ::: "memory")
#define CP_WAIT1()  asm volatile("cp.async.wait_group 1;" ::: "memory")
#define CP_WAIT2()  asm volatile("cp.async.wait_group 2;" ::: "memory")

__device__ __forceinline__ void ldsm4(uint32_t& r0, uint32_t& r1, uint32_t& r2, uint32_t& r3,
                                      uint32_t addr) {
    asm volatile("ldmatrix.sync.aligned.m8n8.x4.shared.b16 {%0,%1,%2,%3}, [%4];"
                 : "=r"(r0), "=r"(r1), "=r"(r2), "=r"(r3) : "r"(addr));
}
__device__ __forceinline__ void ldsm4t(uint32_t& r0, uint32_t& r1, uint32_t& r2, uint32_t& r3,
                                       uint32_t addr) {
    asm volatile("ldmatrix.sync.aligned.m8n8.x4.trans.shared.b16 {%0,%1,%2,%3}, [%4];"
                 : "=r"(r0), "=r"(r1), "=r"(r2), "=r"(r3) : "r"(addr));
}
__device__ __forceinline__ void mma16816(float* c,
                                         uint32_t a0, uint32_t a1, uint32_t a2, uint32_t a3,
                                         uint32_t b0, uint32_t b1) {
    asm volatile("mma.sync.aligned.m16n8k16.row.col.f32.bf16.bf16.f32 "
                 "{%0,%1,%2,%3}, {%4,%5,%6,%7}, {%8,%9}, {%0,%1,%2,%3};"
                 : "+f"(c[0]), "+f"(c[1]), "+f"(c[2]), "+f"(c[3])
                 : "r"(a0), "r"(a1), "r"(a2), "r"(a3), "r"(b0), "r"(b1));
}
__device__ __forceinline__ float ex2f(float x) {
    float y; asm("ex2.approx.f32 %0, %1;" : "=f"(y) : "f"(x)); return y;
}
__device__ __forceinline__ uint32_t packbf(float x, float y) {
    __nv_bfloat162 t = __floats2bfloat162_rn(x, y);
    return *(uint32_t*)&t;
}
__device__ __forceinline__ void hilo2(float v0, float v1, uint32_t& hw, uint32_t& lw) {
    __nv_bfloat16 h0 = __float2bfloat16(v0), h1 = __float2bfloat16(v1);
    __nv_bfloat162 hp = {h0, h1};
    hw = *(uint32_t*)&hp;
    lw = packbf(v0 - __bfloat162float(h0), v1 - __bfloat162float(h1));
}

// ---------------------------------------------------------------------------
// Split fp32 -> (bf16 hi, bf16 lo)
// ---------------------------------------------------------------------------
__global__ __launch_bounds__(256)
void split_kernel(const float* __restrict__ src, __nv_bfloat16* __restrict__ hi,
                  __nv_bfloat16* __restrict__ lo, int n4)
{
    int i = blockIdx.x * 256 + threadIdx.x;
    if (i >= n4) return;
    float4 v = ((const float4*)src)[i];
    uint32_t h0, l0, h1, l1;
    hilo2(v.x, v.y, h0, l0);
    hilo2(v.z, v.w, h1, l1);
    ((uint32_t*)hi)[i*2+0] = h0;  ((uint32_t*)hi)[i*2+1] = h1;
    ((uint32_t*)lo)[i*2+0] = l0;  ((uint32_t*)lo)[i*2+1] = l1;
}

// ---------------------------------------------------------------------------
// bf16x3 GEMM via mma.sync. mode 0: write Q/K/V as bf16 hi/lo (Q scaled by
// 0.125*log2e). mode 1: write fp32 out + bias.
// ---------------------------------------------------------------------------
#define GM_BM 128
#define GM_BN 128
#define GM_BK 32
#define GM_TILES 96            // 3 passes * (1024/32)
#define LSTR 40

#define QSCALE 0.18033688011112042f   // (1/8) * log2(e)

__global__ __launch_bounds__(256)
void gemm_mma_kernel(const __nv_bfloat16* __restrict__ Ah,
                     const __nv_bfloat16* __restrict__ Al,
                     const __nv_bfloat16* __restrict__ Bh,
                     const __nv_bfloat16* __restrict__ Bl,
                     float* __restrict__ outp,
                     const float* __restrict__ bias,
                     int mode)
{
    __shared__ __align__(16) __nv_bfloat16 As[2][GM_BM * LSTR];
    __shared__ __align__(16) __nv_bfloat16 Bs[2][GM_BN * LSTR];

    const int tid = threadIdx.x;
    const int lid = tid & 31;
    const int wid = tid >> 5;
    const int wm = wid >> 2;
    const int wn = wid & 3;

    const int m0 = blockIdx.x * GM_BM;
    const int n0 = blockIdx.y * GM_BN;

    const uint32_t aS = smem_u32(As);
    const uint32_t bS = smem_u32(Bs);
    const uint32_t ABUF = GM_BM * LSTR * 2;
    const uint32_t BBUF = GM_BN * LSTR * 2;

    float acc[4][4][4];
    #pragma unroll
    for (int i = 0; i < 4; i++)
        #pragma unroll
        for (int j = 0; j < 4; j++)
            #pragma unroll
            for (int c = 0; c < 4; c++) acc[i][j][c] = 0.f;

    auto load_tile = [&](int t) {
        const int pass = t >> 5;
        const int k0 = (t & 31) * GM_BK;
        const __nv_bfloat16* Ap = (pass == 1) ? Al : Ah;
        const __nv_bfloat16* Bp = (pass == 2) ? Bl : Bh;
        const int buf = t & 1;
        #pragma unroll
        for (int it = 0; it < 2; it++) {
            int idx = tid + it * 256;
            int row = idx >> 2;
            int ch  = idx & 3;
            cp16(aS + buf * ABUF + (uint32_t)(row * LSTR + ch * 8) * 2,
                 Ap + (size_t)(m0 + row) * DD + k0 + ch * 8);
            cp16(bS + buf * BBUF + (uint32_t)(row * LSTR + ch * 8) * 2,
                 Bp + (size_t)(n0 + row) * DD + k0 + ch * 8);
        }
        CP_COMMIT();
    };

    load_tile(0);
    load_tile(1);

    const int q = lid >> 3;
    const int r = lid & 7;
    const int arow = r + (q & 1) * 8;
    const int acol = (q >> 1) * 8;
    const int brow = r + (q >> 1) * 8;
    const int bcol = (q & 1) * 8;

    for (int i = 0; i < GM_TILES; i++) {
        const int buf = i & 1;
        if (i + 1 < GM_TILES) { CP_WAIT1(); } else { CP_WAIT0(); }
        __syncthreads();

        #pragma unroll
        for (int kst = 0; kst < 2; kst++) {
            const int kb = kst * 16;
            uint32_t a[4][4];
            #pragma unroll
            for (int mt = 0; mt < 4; mt++) {
                uint32_t addr = aS + buf * ABUF +
                    (uint32_t)((wm * 64 + mt * 16 + arow) * LSTR + kb + acol) * 2;
                ldsm4(a[mt][0], a[mt][1], a[mt][2], a[mt][3], addr);
            }
            uint32_t b[4][2];
            #pragma unroll
            for (int np = 0; np < 2; np++) {
                uint32_t addr = bS + buf * BBUF +
                    (uint32_t)((wn * 32 + np * 16 + brow) * LSTR + kb + bcol) * 2;
                ldsm4(b[2*np][0], b[2*np][1], b[2*np+1][0], b[2*np+1][1], addr);
            }
            #pragma unroll
            for (int mt = 0; mt < 4; mt++)
                #pragma unroll
                for (int nt = 0; nt < 4; nt++)
                    mma16816(acc[mt][nt], a[mt][0], a[mt][1], a[mt][2], a[mt][3],
                             b[nt][0], b[nt][1]);
        }
        __syncthreads();
        if (i + 2 < GM_TILES) load_tile(i + 2);
    }

    // Epilogue
    if (mode == 0) {
        const int sel = n0 >> 10;
        __nv_bfloat16* __restrict__ oph = (sel == 0) ? g_qh : (sel == 1) ? g_kh : g_vh;
        __nv_bfloat16* __restrict__ opl = (sel == 0) ? g_ql : (sel == 1) ? g_kl : g_vl;
        const float scale = (sel == 0) ? QSCALE : 1.0f;
        const int ncta = n0 & (DD - 1);
        #pragma unroll
        for (int mt = 0; mt < 4; mt++) {
            int row = m0 + wm * 64 + mt * 16 + (lid >> 2);
            #pragma unroll
            for (int nt = 0; nt < 4; nt++) {
                int col = ncta + wn * 32 + nt * 8 + (lid & 3) * 2;
                uint32_t hw, lw;
                hilo2(acc[mt][nt][0] * scale, acc[mt][nt][1] * scale, hw, lw);
                *(uint32_t*)&oph[(size_t)row * DD + col] = hw;
                *(uint32_t*)&opl[(size_t)row * DD + col] = lw;
                hilo2(acc[mt][nt][2] * scale, acc[mt][nt][3] * scale, hw, lw);
                *(uint32_t*)&oph[(size_t)(row + 8) * DD + col] = hw;
                *(uint32_t*)&opl[(size_t)(row + 8) * DD + col] = lw;
            }
        }
    } else {
        #pragma unroll
        for (int mt = 0; mt < 4; mt++) {
            int row = m0 + wm * 64 + mt * 16 + (lid >> 2);
            #pragma unroll
            for (int nt = 0; nt < 4; nt++) {
                int col = n0 + wn * 32 + nt * 8 + (lid & 3) * 2;
                float2 bb = *(const float2*)&bias[col];
                float2 v0 = {acc[mt][nt][0] + bb.x, acc[mt][nt][1] + bb.y};
                float2 v1 = {acc[mt][nt][2] + bb.x, acc[mt][nt][3] + bb.y};
                *(float2*)&outp[(size_t)row * DD + col] = v0;
                *(float2*)&outp[(size_t)(row + 8) * DD + col] = v1;
            }
        }
    }
}

// ---------------------------------------------------------------------------
// Flash attention (causal) on mma.sync, bf16x3 both products.
// CTA: 128 q-rows (8 warps x 16), k-tiles of 64, cp.async double-buffered.
// Scores are in log2 domain (Q pre-scaled by 0.125*log2e) -> ex2 softmax.
// ---------------------------------------------------------------------------
#define BR 128
#define BC 64
#define KSTR 72                 // padded bf16 stride (144B rows)

#define FQ_OFF  0u              // Q staging hi/lo: 2 * 128*72*2 = 36864
#define FST_OFF 36864u          // stages: 2 * 36864
#define FSTAGE  36864u          // per stage: KH +0, KL +9216, VH +18432, VL +27648
#define FTEN    9216u
#define FSMEM   110592

__global__ __launch_bounds__(256)
void flash_mma_kernel()
{
    extern __shared__ char smem[];
    const uint32_t sb = smem_u32(smem);

    const int tid = threadIdx.x;
    const int lid = tid & 31;
    const int wid = tid >> 5;
    const int itile = blockIdx.x;
    const int bh = blockIdx.y;
    const int b = bh >> 4, h = bh & 15;
    const int qbase = itile * BR;
    const int nkt = 2 * itile + 2;

    const size_t gq  = ((size_t)(b * SS + qbase)) * DD + h * HD;
    const size_t gkv = ((size_t)(b * SS)) * DD + h * HD;

    // --- Q hi/lo -> smem staging ---
    #pragma unroll
    for (int t = 0; t < 8; t++) {
        int idx = tid + t * 256;            // 0..2047
        int ten = idx >> 10;                // 0 = hi, 1 = lo
        int r = (idx >> 3) & 127;
        int c = idx & 7;
        const __nv_bfloat16* src = ten ? g_ql : g_qh;
        cp16(sb + FQ_OFF + (uint32_t)ten * (BR * KSTR * 2) + (uint32_t)(r * KSTR + c * 8) * 2,
             src + gq + (size_t)r * DD + c * 8);
    }
    CP_COMMIT();

    auto load_kv = [&](int kt) {
        const int buf = kt & 1;
        const uint32_t base = sb + FST_OFF + buf * FSTAGE;
        const size_t gk = gkv + (size_t)(kt * BC) * DD;
        #pragma unroll
        for (int t = 0; t < 8; t++) {
            int idx = tid + t * 256;        // 0..2047
            int ten = idx >> 9;             // 0 kh, 1 kl, 2 vh, 3 vl
            int r = (idx >> 3) & 63;
            int c = idx & 7;
            const __nv_bfloat16* src = (ten == 0) ? g_kh : (ten == 1) ? g_kl
                                     : (ten == 2) ? g_vh : g_vl;
            cp16(base + (uint32_t)ten * FTEN + (uint32_t)(r * KSTR + c * 8) * 2,
                 src + gk + (size_t)r * DD + c * 8);
        }
        CP_COMMIT();
    };

    load_kv(0);
    if (nkt > 1) load_kv(1);

    // --- Q fragments (register resident) ---
    CP_WAIT2();                 // Q group done (2 kv groups may be pending)
    __syncthreads();

    const int q4 = lid >> 3;
    const int r8 = lid & 7;
    const int arow = r8 + (q4 & 1) * 8;
    const int acol = (q4 >> 1) * 8;
    const int brow = r8 + (q4 >> 1) * 8;
    const int bcol = (q4 & 1) * 8;

    uint32_t qh[4][4], ql[4][4];
    #pragma unroll
    for (int ks = 0; ks < 4; ks++) {
        uint32_t ao = (uint32_t)((wid * 16 + arow) * KSTR + ks * 16 + acol) * 2;
        ldsm4(qh[ks][0], qh[ks][1], qh[ks][2], qh[ks][3], sb + FQ_OFF + ao);
        ldsm4(ql[ks][0], ql[ks][1], ql[ks][2], ql[ks][3], sb + FQ_OFF + BR * KSTR * 2 + ao);
    }

    float o[8][4];
    #pragma unroll
    for (int nf = 0; nf < 8; nf++)
        #pragma unroll
        for (int c = 0; c < 4; c++) o[nf][c] = 0.f;
    float m0 = -1e30f, m1 = -1e30f, ls0 = 0.f, ls1 = 0.f;

    const int rowg = qbase + wid * 16 + (lid >> 2);   // thread's row (and +8)

    for (int kt = 0; kt < nkt; kt++) {
        const int buf = kt & 1;
        if (kt + 1 < nkt) { CP_WAIT1(); } else { CP_WAIT0(); }
        __syncthreads();

        const uint32_t kb = sb + FST_OFF + buf * FSTAGE;

        // ---- S = Q K^T (bf16x3) ----
        float s[8][4];
        #pragma unroll
        for (int nf = 0; nf < 8; nf++)
            #pragma unroll
            for (int c = 0; c < 4; c++) s[nf][c] = 0.f;

        #pragma unroll
        for (int ks = 0; ks < 4; ks++) {
            #pragma unroll
            for (int np = 0; np < 4; np++) {
                uint32_t ao = (uint32_t)((np * 16 + brow) * KSTR + ks * 16 + bcol) * 2;
                uint32_t k0, k1, k2, k3, l0, l1, l2, l3;
                ldsm4(k0, k1, k2, k3, kb + ao);           // KH
                ldsm4(l0, l1, l2, l3, kb + FTEN + ao);    // KL
                mma16816(s[2*np],   qh[ks][0], qh[ks][1], qh[ks][2], qh[ks][3], k0, k1);
                mma16816(s[2*np+1], qh[ks][0], qh[ks][1], qh[ks][2], qh[ks][3], k2, k3);
                mma16816(s[2*np],   ql[ks][0], ql[ks][1], ql[ks][2], ql[ks][3], k0, k1);
                mma16816(s[2*np+1], ql[ks][0], ql[ks][1], ql[ks][2], ql[ks][3], k2, k3);
                mma16816(s[2*np],   qh[ks][0], qh[ks][1], qh[ks][2], qh[ks][3], l0, l1);
                mma16816(s[2*np+1], qh[ks][0], qh[ks][1], qh[ks][2], qh[ks][3], l2, l3);
            }
        }

        // ---- causal mask on the last two k-tiles ----
        if (kt >= nkt - 2) {
            const int colb = kt * BC + (lid & 3) * 2;
            #pragma unroll
            for (int nf = 0; nf < 8; nf++) {
                int c0 = colb + nf * 8;
                if (c0     > rowg)     s[nf][0] = -1e30f;
                if (c0 + 1 > rowg)     s[nf][1] = -1e30f;
                if (c0     > rowg + 8) s[nf][2] = -1e30f;
                if (c0 + 1 > rowg + 8) s[nf][3] = -1e30f;
            }
        }

        // ---- online softmax (log2 domain) ----
        float mx0 = -1e30f, mx1 = -1e30f;
        #pragma unroll
        for (int nf = 0; nf < 8; nf++) {
            mx0 = fmaxf(mx0, fmaxf(s[nf][0], s[nf][1]));
            mx1 = fmaxf(mx1, fmaxf(s[nf][2], s[nf][3]));
        }
        mx0 = fmaxf(mx0, __shfl_xor_sync(0xffffffffu, mx0, 1));
        mx0 = fmaxf(mx0, __shfl_xor_sync(0xffffffffu, mx0, 2));
        mx1 = fmaxf(mx1, __shfl_xor_sync(0xffffffffu, mx1, 1));
        mx1 = fmaxf(mx1, __shfl_xor_sync(0xffffffffu, mx1, 2));
        const float nm0 = fmaxf(m0, mx0), nm1 = fmaxf(m1, mx1);
        const float al0 = ex2f(m0 - nm0), al1 = ex2f(m1 - nm1);
        m0 = nm0; m1 = nm1;
        ls0 *= al0; ls1 *= al1;

        #pragma unroll
        for (int nf = 0; nf < 8; nf++) {
            s[nf][0] = ex2f(s[nf][0] - m0);
            s[nf][1] = ex2f(s[nf][1] - m0);
            s[nf][2] = ex2f(s[nf][2] - m1);
            s[nf][3] = ex2f(s[nf][3] - m1);
            ls0 += s[nf][0] + s[nf][1];
            ls1 += s[nf][2] + s[nf][3];
        }
        #pragma unroll
        for (int nf = 0; nf < 8; nf++) {
            o[nf][0] *= al0; o[nf][1] *= al0;
            o[nf][2] *= al1; o[nf][3] *= al1;
        }

        // ---- O += P V (bf16x3) ----
        const int vlane_r = lid & 15;
        const int vlane_c = (lid >> 4) * 8;
        #pragma unroll
        for (int ks = 0; ks < 4; ks++) {
            // P a-fragments for keys 16ks..16ks+15 (hi and lo)
            uint32_t pa[4], pb[4];
            {
                float p00 = s[2*ks][0],   p01 = s[2*ks][1];
                float p10 = s[2*ks][2],   p11 = s[2*ks][3];
                float p20 = s[2*ks+1][0], p21 = s[2*ks+1][1];
                float p30 = s[2*ks+1][2], p31 = s[2*ks+1][3];
                hilo2(p00, p01, pa[0], pb[0]);
                hilo2(p10, p11, pa[1], pb[1]);
                hilo2(p20, p21, pa[2], pb[2]);
                hilo2(p30, p31, pa[3], pb[3]);
            }
            #pragma unroll
            for (int np = 0; np < 4; np++) {
                uint32_t ao = (uint32_t)((ks * 16 + vlane_r) * KSTR + np * 16 + vlane_c) * 2;
                uint32_t v0, v1, v2, v3, w0, w1, w2, w3;
                ldsm4t(v0, v1, v2, v3, kb + 2 * FTEN + ao);   // VH
                ldsm4t(w0, w1, w2, w3, kb + 3 * FTEN + ao);   // VL
                mma16816(o[2*np],   pa[0], pa[1], pa[2], pa[3], v0, v1);
                mma16816(o[2*np+1], pa[0], pa[1], pa[2], pa[3], v2, v3);
                mma16816(o[2*np],   pb[0], pb[1], pb[2], pb[3], v0, v1);
                mma16816(o[2*np+1], pb[0], pb[1], pb[2], pb[3], v2, v3);
                mma16816(o[2*np],   pa[0], pa[1], pa[2], pa[3], w0, w1);
                mma16816(o[2*np+1], pa[0], pa[1], pa[2], pa[3], w2, w3);
            }
        }

        __syncthreads();
        if (kt + 2 < nkt) load_kv(kt + 2);
    }

    // ---- epilogue: normalize, write ctx hi/lo ----
    ls0 += __shfl_xor_sync(0xffffffffu, ls0, 1);
    ls0 += __shfl_xor_sync(0xffffffffu, ls0, 2);
    ls1 += __shfl_xor_sync(0xffffffffu, ls1, 1);
    ls1 += __shfl_xor_sync(0xffffffffu, ls1, 2);
    const float li0 = 1.0f / ls0, li1 = 1.0f / ls1;

    const size_t row0 = (size_t)(b * SS + rowg);
    const int colb = h * HD + (lid & 3) * 2;
    #pragma unroll
    for (int nf = 0; nf < 8; nf++) {
        int col = colb + nf * 8;
        uint32_t hw, lw;
        hilo2(o[nf][0] * li0, o[nf][1] * li0, hw, lw);
        *(uint32_t*)&g_ch[row0 * DD + col] = hw;
        *(uint32_t*)&g_cl[row0 * DD + col] = lw;
        hilo2(o[nf][2] * li1, o[nf][3] * li1, hw, lw);
        *(uint32_t*)&g_ch[(row0 + 8) * DD + col] = hw;
        *(uint32_t*)&g_cl[(row0 + 8) * DD + col] = lw;
    }
}

// ---------------------------------------------------------------------------

extern "C" void kernel_launch(void* const* d_in, const int* in_sizes, int n_in,
                              void* d_out, int out_size)
{
    const float* x    = (const float*)d_in[0];
    const float* wq   = (const float*)d_in[1];
    const float* wk   = (const float*)d_in[2];
    const float* wv   = (const float*)d_in[3];
    const float* wo   = (const float*)d_in[4];
    const float* wo_b = (const float*)d_in[5];
    float* out = (float*)d_out;

    static int attr_done = 0;
    if (!attr_done) {
        cudaFuncSetAttribute(flash_mma_kernel,
                             cudaFuncAttributeMaxDynamicSharedMemorySize, FSMEM);
        attr_done = 1;
    }

    __nv_bfloat16 *xh, *xl, *wh, *wl, *woh, *wol, *ch, *cl;
    cudaGetSymbolAddress((void**)&xh,  g_xh);
    cudaGetSymbolAddress((void**)&xl,  g_xl);
    cudaGetSymbolAddress((void**)&wh,  g_wh);
    cudaGetSymbolAddress((void**)&wl,  g_wl);
    cudaGetSymbolAddress((void**)&woh, g_woh);
    cudaGetSymbolAddress((void**)&wol, g_wol);
    cudaGetSymbolAddress((void**)&ch,  g_ch);
    cudaGetSymbolAddress((void**)&cl,  g_cl);

    // 1. split inputs to bf16 hi/lo
    split_kernel<<<(BS*DD/4 + 255)/256, 256>>>(x, xh, xl, BS*DD/4);
    split_kernel<<<(DD*DD/4 + 255)/256, 256>>>(wq, wh,           wl,           DD*DD/4);
    split_kernel<<<(DD*DD/4 + 255)/256, 256>>>(wk, wh + DD*DD,   wl + DD*DD,   DD*DD/4);
    split_kernel<<<(DD*DD/4 + 255)/256, 256>>>(wv, wh + 2*DD*DD, wl + 2*DD*DD, DD*DD/4);
    split_kernel<<<(DD*DD/4 + 255)/256, 256>>>(wo, woh, wol, DD*DD/4);

    // 2. fused QKV projection -> bf16 hi/lo Q/K/V (Q pre-scaled, log2e folded)
    gemm_mma_kernel<<<dim3(BS/GM_BM, 3*DD/GM_BN), 256>>>(
        xh, xl, wh, wl, nullptr, nullptr, 0);

    // 3. causal flash attention on tensor cores -> ctx bf16 hi/lo
    flash_mma_kernel<<<dim3(SS/BR, BB*HH), 256, FSMEM>>>();

    // 4. output projection + bias (fp32 out)
    gemm_mma_kernel<<<dim3(BS/GM_BM, DD/GM_BN), 256>>>(
        ch, cl, woh, wol, out, wo_b, 1);
}

// round 5
// speedup vs baseline: 3.4407x; 1.2713x over previous
#include <cuda_runtime.h>
#include <cuda_bf16.h>
#include <cuda_fp16.h>
#include <cstdint>

// Problem constants
#define BB 4
#define SS 2048
#define DD 1024
#define HH 16
#define HD 64
#define BS (BB*SS)          // 8192

// ---------------------------------------------------------------------------
// Scratch (device globals; no allocation allowed)
// ---------------------------------------------------------------------------
__device__ __half g_xh16[BS*DD], g_xl16[BS*DD];             // x split (fp16 hi/lo)
__device__ __half g_w16[3*DD*DD];                           // fused Wq|Wk|Wv fp16
__device__ __half g_wo16[DD*DD];                            // Wo fp16
__device__ __half g_ch16[BS*DD], g_cl16[BS*DD];             // ctx split (fp16 hi/lo)

__device__ __nv_bfloat16 g_qh[BS*DD], g_ql[BS*DD];          // Q (scaled) bf16 hi/lo
__device__ __nv_bfloat16 g_kh[BS*DD], g_kl[BS*DD];
__device__ __nv_bfloat16 g_vh[BS*DD], g_vl[BS*DD];

// ---------------------------------------------------------------------------
// Portable (compute_103-safe) PTX helpers
// ---------------------------------------------------------------------------
__device__ __forceinline__ uint32_t smem_u32(const void* p) {
    uint32_t a;
    asm("{ .reg .u64 t; cvta.to.shared.u64 t, %1; cvt.u32.u64 %0, t; }" : "=r"(a) : "l"(p));
    return a;
}
__device__ __forceinline__ void cp16(uint32_t dst, const void* src) {
    asm volatile("cp.async.cg.shared.global [%0], [%1], 16;" :: "r"(dst), "l"(src) : "memory");
}
#define CP_COMMIT() asm volatile("cp.async.commit_group;" ::: "memory")
#define CP_WAIT0()  asm volatile("cp.async.wait_group 0;" ::: "memory")
#define CP_WAIT1()  asm volatile("cp.async.wait_group 1;" ::: "memory")
#define CP_WAIT2()  asm volatile("cp.async.wait_group 2;" ::: "memory")

__device__ __forceinline__ void ldsm4(uint32_t& r0, uint32_t& r1, uint32_t& r2, uint32_t& r3,
                                      uint32_t addr) {
    asm volatile("ldmatrix.sync.aligned.m8n8.x4.shared.b16 {%0,%1,%2,%3}, [%4];"
                 : "=r"(r0), "=r"(r1), "=r"(r2), "=r"(r3) : "r"(addr));
}
__device__ __forceinline__ void ldsm4t(uint32_t& r0, uint32_t& r1, uint32_t& r2, uint32_t& r3,
                                       uint32_t addr) {
    asm volatile("ldmatrix.sync.aligned.m8n8.x4.trans.shared.b16 {%0,%1,%2,%3}, [%4];"
                 : "=r"(r0), "=r"(r1), "=r"(r2), "=r"(r3) : "r"(addr));
}
// bf16 mma (flash)
__device__ __forceinline__ void mma16816(float* c,
                                         uint32_t a0, uint32_t a1, uint32_t a2, uint32_t a3,
                                         uint32_t b0, uint32_t b1) {
    asm volatile("mma.sync.aligned.m16n8k16.row.col.f32.bf16.bf16.f32 "
                 "{%0,%1,%2,%3}, {%4,%5,%6,%7}, {%8,%9}, {%0,%1,%2,%3};"
                 : "+f"(c[0]), "+f"(c[1]), "+f"(c[2]), "+f"(c[3])
                 : "r"(a0), "r"(a1), "r"(a2), "r"(a3), "r"(b0), "r"(b1));
}
// fp16 mma (GEMMs)
__device__ __forceinline__ void mma16816h(float* c,
                                          uint32_t a0, uint32_t a1, uint32_t a2, uint32_t a3,
                                          uint32_t b0, uint32_t b1) {
    asm volatile("mma.sync.aligned.m16n8k16.row.col.f32.f16.f16.f32 "
                 "{%0,%1,%2,%3}, {%4,%5,%6,%7}, {%8,%9}, {%0,%1,%2,%3};"
                 : "+f"(c[0]), "+f"(c[1]), "+f"(c[2]), "+f"(c[3])
                 : "r"(a0), "r"(a1), "r"(a2), "r"(a3), "r"(b0), "r"(b1));
}
__device__ __forceinline__ float ex2f(float x) {
    float y; asm("ex2.approx.f32 %0, %1;" : "=f"(y) : "f"(x)); return y;
}
__device__ __forceinline__ uint32_t packbf(float x, float y) {
    __nv_bfloat162 t = __floats2bfloat162_rn(x, y);
    return *(uint32_t*)&t;
}
// bf16 hi/lo split of a pair
__device__ __forceinline__ void hilo2(float v0, float v1, uint32_t& hw, uint32_t& lw) {
    __nv_bfloat16 h0 = __float2bfloat16(v0), h1 = __float2bfloat16(v1);
    __nv_bfloat162 hp = {h0, h1};
    hw = *(uint32_t*)&hp;
    lw = packbf(v0 - __bfloat162float(h0), v1 - __bfloat162float(h1));
}
// fp16 hi/lo split of a pair
__device__ __forceinline__ void hilo2h(float v0, float v1, uint32_t& hw, uint32_t& lw) {
    __half h0 = __float2half_rn(v0), h1 = __float2half_rn(v1);
    __half2 hp = {h0, h1};
    hw = *(uint32_t*)&hp;
    __half2 lp = __floats2half2_rn(v0 - __half2float(h0), v1 - __half2float(h1));
    lw = *(uint32_t*)&lp;
}

// ---------------------------------------------------------------------------
// fp32 -> fp16 hi/lo split (activations)
// ---------------------------------------------------------------------------
__global__ __launch_bounds__(256)
void split16_kernel(const float* __restrict__ src, __half* __restrict__ hi,
                    __half* __restrict__ lo, int n4)
{
    int i = blockIdx.x * 256 + threadIdx.x;
    if (i >= n4) return;
    float4 v = ((const float4*)src)[i];
    uint32_t h0, l0, h1, l1;
    hilo2h(v.x, v.y, h0, l0);
    hilo2h(v.z, v.w, h1, l1);
    ((uint32_t*)hi)[i*2+0] = h0;  ((uint32_t*)hi)[i*2+1] = h1;
    ((uint32_t*)lo)[i*2+0] = l0;  ((uint32_t*)lo)[i*2+1] = l1;
}

// fp32 -> fp16 convert (weights)
__global__ __launch_bounds__(256)
void cvt16_kernel(const float* __restrict__ src, __half* __restrict__ dst, int n4)
{
    int i = blockIdx.x * 256 + threadIdx.x;
    if (i >= n4) return;
    float4 v = ((const float4*)src)[i];
    __half2 p0 = __floats2half2_rn(v.x, v.y);
    __half2 p1 = __floats2half2_rn(v.z, v.w);
    ((uint32_t*)dst)[i*2+0] = *(uint32_t*)&p0;
    ((uint32_t*)dst)[i*2+1] = *(uint32_t*)&p1;
}

// ---------------------------------------------------------------------------
// fp16 2-pass GEMM via mma.sync: C = (Ah + Al) * B^T, B fp16 single.
// CTA 128x128, BK=32, 3-stage cp.async, 8 warps (2M x 4N), warp 64x32.
// mode 0: write Q/K/V as bf16 hi/lo (Q scaled 0.125*log2e); mode 1: fp32 + bias
// ---------------------------------------------------------------------------
#define GM_BM 128
#define GM_BN 128
#define GM_BK 32
#define GM_TILES 32            // K=1024 / 32
#define LSTR 40                // smem row stride in halves (80B)

#define TEN_B  10240u          // bytes per 128x32 fp16 tensor (LSTR-padded)
#define STG_B  30720u          // Ah + Al + B per stage
#define GSMEM  92160           // 3 stages

#define QSCALE 0.18033688011112042f   // (1/8) * log2(e)

__global__ __launch_bounds__(256)
void gemm_fp16_kernel(const __half* __restrict__ Ah,
                      const __half* __restrict__ Al,
                      const __half* __restrict__ Bw,
                      float* __restrict__ outp,
                      const float* __restrict__ bias,
                      int mode)
{
    extern __shared__ char smem[];
    const uint32_t sb = smem_u32(smem);

    const int tid = threadIdx.x;
    const int lid = tid & 31;
    const int wid = tid >> 5;
    const int wm = wid >> 2;
    const int wn = wid & 3;

    const int m0 = blockIdx.x * GM_BM;
    const int n0 = blockIdx.y * GM_BN;

    float acc[4][4][4];
    #pragma unroll
    for (int i = 0; i < 4; i++)
        #pragma unroll
        for (int j = 0; j < 4; j++)
            #pragma unroll
            for (int c = 0; c < 4; c++) acc[i][j][c] = 0.f;

    auto load_tile = [&](int t) {
        const int k0 = t * GM_BK;
        const uint32_t base = sb + (uint32_t)(t % 3) * STG_B;
        #pragma unroll
        for (int it = 0; it < 6; it++) {
            int idx = tid + it * 256;         // 0..1535
            int ten = idx >> 9;               // 0 = Ah, 1 = Al, 2 = B
            int r = (idx >> 2) & 127;
            int c = idx & 3;
            const __half* src = (ten == 0) ? Ah : (ten == 1) ? Al : Bw;
            const int row = (ten == 2) ? (n0 + r) : (m0 + r);
            cp16(base + (uint32_t)ten * TEN_B + (uint32_t)(r * LSTR + c * 8) * 2,
                 src + (size_t)row * DD + k0 + c * 8);
        }
        CP_COMMIT();
    };

    load_tile(0);
    load_tile(1);

    const int q = lid >> 3;
    const int r = lid & 7;
    const int arow = r + (q & 1) * 8;
    const int acol = (q >> 1) * 8;
    const int brow = r + (q >> 1) * 8;
    const int bcol = (q & 1) * 8;

    for (int i = 0; i < GM_TILES; i++) {
        if (i + 1 < GM_TILES) { CP_WAIT1(); } else { CP_WAIT0(); }
        __syncthreads();
        if (i + 2 < GM_TILES) load_tile(i + 2);

        const uint32_t stg = sb + (uint32_t)(i % 3) * STG_B;

        #pragma unroll
        for (int kst = 0; kst < 2; kst++) {
            const int kb = kst * 16;
            uint32_t b[4][2];
            #pragma unroll
            for (int np = 0; np < 2; np++) {
                uint32_t addr = stg + 2 * TEN_B +
                    (uint32_t)((wn * 32 + np * 16 + brow) * LSTR + kb + bcol) * 2;
                ldsm4(b[2*np][0], b[2*np][1], b[2*np+1][0], b[2*np+1][1], addr);
            }
            uint32_t a[4][4];
            #pragma unroll
            for (int mt = 0; mt < 4; mt++) {
                uint32_t addr = stg +
                    (uint32_t)((wm * 64 + mt * 16 + arow) * LSTR + kb + acol) * 2;
                ldsm4(a[mt][0], a[mt][1], a[mt][2], a[mt][3], addr);
            }
            #pragma unroll
            for (int mt = 0; mt < 4; mt++)
                #pragma unroll
                for (int nt = 0; nt < 4; nt++)
                    mma16816h(acc[mt][nt], a[mt][0], a[mt][1], a[mt][2], a[mt][3],
                              b[nt][0], b[nt][1]);
            #pragma unroll
            for (int mt = 0; mt < 4; mt++) {
                uint32_t addr = stg + TEN_B +
                    (uint32_t)((wm * 64 + mt * 16 + arow) * LSTR + kb + acol) * 2;
                ldsm4(a[mt][0], a[mt][1], a[mt][2], a[mt][3], addr);
            }
            #pragma unroll
            for (int mt = 0; mt < 4; mt++)
                #pragma unroll
                for (int nt = 0; nt < 4; nt++)
                    mma16816h(acc[mt][nt], a[mt][0], a[mt][1], a[mt][2], a[mt][3],
                              b[nt][0], b[nt][1]);
        }
    }

    // Epilogue
    if (mode == 0) {
        const int sel = n0 >> 10;
        __nv_bfloat16* __restrict__ oph = (sel == 0) ? g_qh : (sel == 1) ? g_kh : g_vh;
        __nv_bfloat16* __restrict__ opl = (sel == 0) ? g_ql : (sel == 1) ? g_kl : g_vl;
        const float scale = (sel == 0) ? QSCALE : 1.0f;
        const int ncta = n0 & (DD - 1);
        #pragma unroll
        for (int mt = 0; mt < 4; mt++) {
            int row = m0 + wm * 64 + mt * 16 + (lid >> 2);
            #pragma unroll
            for (int nt = 0; nt < 4; nt++) {
                int col = ncta + wn * 32 + nt * 8 + (lid & 3) * 2;
                uint32_t hw, lw;
                hilo2(acc[mt][nt][0] * scale, acc[mt][nt][1] * scale, hw, lw);
                *(uint32_t*)&oph[(size_t)row * DD + col] = hw;
                *(uint32_t*)&opl[(size_t)row * DD + col] = lw;
                hilo2(acc[mt][nt][2] * scale, acc[mt][nt][3] * scale, hw, lw);
                *(uint32_t*)&oph[(size_t)(row + 8) * DD + col] = hw;
                *(uint32_t*)&opl[(size_t)(row + 8) * DD + col] = lw;
            }
        }
    } else {
        #pragma unroll
        for (int mt = 0; mt < 4; mt++) {
            int row = m0 + wm * 64 + mt * 16 + (lid >> 2);
            #pragma unroll
            for (int nt = 0; nt < 4; nt++) {
                int col = n0 + wn * 32 + nt * 8 + (lid & 3) * 2;
                float2 bb = *(const float2*)&bias[col];
                float2 v0 = {acc[mt][nt][0] + bb.x, acc[mt][nt][1] + bb.y};
                float2 v1 = {acc[mt][nt][2] + bb.x, acc[mt][nt][3] + bb.y};
                *(float2*)&outp[(size_t)row * DD + col] = v0;
                *(float2*)&outp[(size_t)(row + 8) * DD + col] = v1;
            }
        }
    }
}

// ---------------------------------------------------------------------------
// Flash attention (causal) on mma.sync, bf16x3 both products. (round-4 proven)
// ctx epilogue writes fp16 hi/lo for the oproj GEMM.
// ---------------------------------------------------------------------------
#define BR 128
#define BC 64
#define KSTR 72

#define FQ_OFF  0u
#define FST_OFF 36864u
#define FSTAGE  36864u
#define FTEN    9216u
#define FSMEM   110592

__global__ __launch_bounds__(256)
void flash_mma_kernel()
{
    extern __shared__ char smem[];
    const uint32_t sb = smem_u32(smem);

    const int tid = threadIdx.x;
    const int lid = tid & 31;
    const int wid = tid >> 5;
    const int itile = blockIdx.x;
    const int bh = blockIdx.y;
    const int b = bh >> 4, h = bh & 15;
    const int qbase = itile * BR;
    const int nkt = 2 * itile + 2;

    const size_t gq  = ((size_t)(b * SS + qbase)) * DD + h * HD;
    const size_t gkv = ((size_t)(b * SS)) * DD + h * HD;

    #pragma unroll
    for (int t = 0; t < 8; t++) {
        int idx = tid + t * 256;
        int ten = idx >> 10;
        int r = (idx >> 3) & 127;
        int c = idx & 7;
        const __nv_bfloat16* src = ten ? g_ql : g_qh;
        cp16(sb + FQ_OFF + (uint32_t)ten * (BR * KSTR * 2) + (uint32_t)(r * KSTR + c * 8) * 2,
             src + gq + (size_t)r * DD + c * 8);
    }
    CP_COMMIT();

    auto load_kv = [&](int kt) {
        const int buf = kt & 1;
        const uint32_t base = sb + FST_OFF + buf * FSTAGE;
        const size_t gk = gkv + (size_t)(kt * BC) * DD;
        #pragma unroll
        for (int t = 0; t < 8; t++) {
            int idx = tid + t * 256;
            int ten = idx >> 9;
            int r = (idx >> 3) & 63;
            int c = idx & 7;
            const __nv_bfloat16* src = (ten == 0) ? g_kh : (ten == 1) ? g_kl
                                     : (ten == 2) ? g_vh : g_vl;
            cp16(base + (uint32_t)ten * FTEN + (uint32_t)(r * KSTR + c * 8) * 2,
                 src + gk + (size_t)r * DD + c * 8);
        }
        CP_COMMIT();
    };

    load_kv(0);
    if (nkt > 1) load_kv(1);

    CP_WAIT2();
    __syncthreads();

    const int q4 = lid >> 3;
    const int r8 = lid & 7;
    const int arow = r8 + (q4 & 1) * 8;
    const int acol = (q4 >> 1) * 8;
    const int brow = r8 + (q4 >> 1) * 8;
    const int bcol = (q4 & 1) * 8;

    uint32_t qh[4][4], ql[4][4];
    #pragma unroll
    for (int ks = 0; ks < 4; ks++) {
        uint32_t ao = (uint32_t)((wid * 16 + arow) * KSTR + ks * 16 + acol) * 2;
        ldsm4(qh[ks][0], qh[ks][1], qh[ks][2], qh[ks][3], sb + FQ_OFF + ao);
        ldsm4(ql[ks][0], ql[ks][1], ql[ks][2], ql[ks][3], sb + FQ_OFF + BR * KSTR * 2 + ao);
    }

    float o[8][4];
    #pragma unroll
    for (int nf = 0; nf < 8; nf++)
        #pragma unroll
        for (int c = 0; c < 4; c++) o[nf][c] = 0.f;
    float m0 = -1e30f, m1 = -1e30f, ls0 = 0.f, ls1 = 0.f;

    const int rowg = qbase + wid * 16 + (lid >> 2);

    for (int kt = 0; kt < nkt; kt++) {
        const int buf = kt & 1;
        if (kt + 1 < nkt) { CP_WAIT1(); } else { CP_WAIT0(); }
        __syncthreads();

        const uint32_t kb = sb + FST_OFF + buf * FSTAGE;

        float s[8][4];
        #pragma unroll
        for (int nf = 0; nf < 8; nf++)
            #pragma unroll
            for (int c = 0; c < 4; c++) s[nf][c] = 0.f;

        #pragma unroll
        for (int ks = 0; ks < 4; ks++) {
            #pragma unroll
            for (int np = 0; np < 4; np++) {
                uint32_t ao = (uint32_t)((np * 16 + brow) * KSTR + ks * 16 + bcol) * 2;
                uint32_t k0, k1, k2, k3, l0, l1, l2, l3;
                ldsm4(k0, k1, k2, k3, kb + ao);
                ldsm4(l0, l1, l2, l3, kb + FTEN + ao);
                mma16816(s[2*np],   qh[ks][0], qh[ks][1], qh[ks][2], qh[ks][3], k0, k1);
                mma16816(s[2*np+1], qh[ks][0], qh[ks][1], qh[ks][2], qh[ks][3], k2, k3);
                mma16816(s[2*np],   ql[ks][0], ql[ks][1], ql[ks][2], ql[ks][3], k0, k1);
                mma16816(s[2*np+1], ql[ks][0], ql[ks][1], ql[ks][2], ql[ks][3], k2, k3);
                mma16816(s[2*np],   qh[ks][0], qh[ks][1], qh[ks][2], qh[ks][3], l0, l1);
                mma16816(s[2*np+1], qh[ks][0], qh[ks][1], qh[ks][2], qh[ks][3], l2, l3);
            }
        }

        if (kt >= nkt - 2) {
            const int colb = kt * BC + (lid & 3) * 2;
            #pragma unroll
            for (int nf = 0; nf < 8; nf++) {
                int c0 = colb + nf * 8;
                if (c0     > rowg)     s[nf][0] = -1e30f;
                if (c0 + 1 > rowg)     s[nf][1] = -1e30f;
                if (c0     > rowg + 8) s[nf][2] = -1e30f;
                if (c0 + 1 > rowg + 8) s[nf][3] = -1e30f;
            }
        }

        float mx0 = -1e30f, mx1 = -1e30f;
        #pragma unroll
        for (int nf = 0; nf < 8; nf++) {
            mx0 = fmaxf(mx0, fmaxf(s[nf][0], s[nf][1]));
            mx1 = fmaxf(mx1, fmaxf(s[nf][2], s[nf][3]));
        }
        mx0 = fmaxf(mx0, __shfl_xor_sync(0xffffffffu, mx0, 1));
        mx0 = fmaxf(mx0, __shfl_xor_sync(0xffffffffu, mx0, 2));
        mx1 = fmaxf(mx1, __shfl_xor_sync(0xffffffffu, mx1, 1));
        mx1 = fmaxf(mx1, __shfl_xor_sync(0xffffffffu, mx1, 2));
        const float nm0 = fmaxf(m0, mx0), nm1 = fmaxf(m1, mx1);
        const float al0 = ex2f(m0 - nm0), al1 = ex2f(m1 - nm1);
        m0 = nm0; m1 = nm1;
        ls0 *= al0; ls1 *= al1;

        #pragma unroll
        for (int nf = 0; nf < 8; nf++) {
            s[nf][0] = ex2f(s[nf][0] - m0);
            s[nf][1] = ex2f(s[nf][1] - m0);
            s[nf][2] = ex2f(s[nf][2] - m1);
            s[nf][3] = ex2f(s[nf][3] - m1);
            ls0 += s[nf][0] + s[nf][1];
            ls1 += s[nf][2] + s[nf][3];
        }
        #pragma unroll
        for (int nf = 0; nf < 8; nf++) {
            o[nf][0] *= al0; o[nf][1] *= al0;
            o[nf][2] *= al1; o[nf][3] *= al1;
        }

        const int vlane_r = lid & 15;
        const int vlane_c = (lid >> 4) * 8;
        #pragma unroll
        for (int ks = 0; ks < 4; ks++) {
            uint32_t pa[4], pb[4];
            {
                hilo2(s[2*ks][0],   s[2*ks][1],   pa[0], pb[0]);
                hilo2(s[2*ks][2],   s[2*ks][3],   pa[1], pb[1]);
                hilo2(s[2*ks+1][0], s[2*ks+1][1], pa[2], pb[2]);
                hilo2(s[2*ks+1][2], s[2*ks+1][3], pa[3], pb[3]);
            }
            #pragma unroll
            for (int np = 0; np < 4; np++) {
                uint32_t ao = (uint32_t)((ks * 16 + vlane_r) * KSTR + np * 16 + vlane_c) * 2;
                uint32_t v0, v1, v2, v3, w0, w1, w2, w3;
                ldsm4t(v0, v1, v2, v3, kb + 2 * FTEN + ao);
                ldsm4t(w0, w1, w2, w3, kb + 3 * FTEN + ao);
                mma16816(o[2*np],   pa[0], pa[1], pa[2], pa[3], v0, v1);
                mma16816(o[2*np+1], pa[0], pa[1], pa[2], pa[3], v2, v3);
                mma16816(o[2*np],   pb[0], pb[1], pb[2], pb[3], v0, v1);
                mma16816(o[2*np+1], pb[0], pb[1], pb[2], pb[3], v2, v3);
                mma16816(o[2*np],   pa[0], pa[1], pa[2], pa[3], w0, w1);
                mma16816(o[2*np+1], pa[0], pa[1], pa[2], pa[3], w2, w3);
            }
        }

        __syncthreads();
        if (kt + 2 < nkt) load_kv(kt + 2);
    }

    ls0 += __shfl_xor_sync(0xffffffffu, ls0, 1);
    ls0 += __shfl_xor_sync(0xffffffffu, ls0, 2);
    ls1 += __shfl_xor_sync(0xffffffffu, ls1, 1);
    ls1 += __shfl_xor_sync(0xffffffffu, ls1, 2);
    const float li0 = 1.0f / ls0, li1 = 1.0f / ls1;

    const size_t row0 = (size_t)(b * SS + rowg);
    const int colb = h * HD + (lid & 3) * 2;
    #pragma unroll
    for (int nf = 0; nf < 8; nf++) {
        int col = colb + nf * 8;
        uint32_t hw, lw;
        hilo2h(o[nf][0] * li0, o[nf][1] * li0, hw, lw);
        *(uint32_t*)&g_ch16[row0 * DD + col] = hw;
        *(uint32_t*)&g_cl16[row0 * DD + col] = lw;
        hilo2h(o[nf][2] * li1, o[nf][3] * li1, hw, lw);
        *(uint32_t*)&g_ch16[(row0 + 8) * DD + col] = hw;
        *(uint32_t*)&g_cl16[(row0 + 8) * DD + col] = lw;
    }
}

// ---------------------------------------------------------------------------

extern "C" void kernel_launch(void* const* d_in, const int* in_sizes, int n_in,
                              void* d_out, int out_size)
{
    const float* x    = (const float*)d_in[0];
    const float* wq   = (const float*)d_in[1];
    const float* wk   = (const float*)d_in[2];
    const float* wv   = (const float*)d_in[3];
    const float* wo   = (const float*)d_in[4];
    const float* wo_b = (const float*)d_in[5];
    float* out = (float*)d_out;

    static int attr_done = 0;
    if (!attr_done) {
        cudaFuncSetAttribute(flash_mma_kernel,
                             cudaFuncAttributeMaxDynamicSharedMemorySize, FSMEM);
        cudaFuncSetAttribute(gemm_fp16_kernel,
                             cudaFuncAttributeMaxDynamicSharedMemorySize, GSMEM);
        attr_done = 1;
    }

    __half *xh, *xl, *w16, *wo16, *ch, *cl;
    cudaGetSymbolAddress((void**)&xh,   g_xh16);
    cudaGetSymbolAddress((void**)&xl,   g_xl16);
    cudaGetSymbolAddress((void**)&w16,  g_w16);
    cudaGetSymbolAddress((void**)&wo16, g_wo16);
    cudaGetSymbolAddress((void**)&ch,   g_ch16);
    cudaGetSymbolAddress((void**)&cl,   g_cl16);

    // 1. split x (fp16 hi/lo); convert weights to fp16
    split16_kernel<<<(BS*DD/4 + 255)/256, 256>>>(x, xh, xl, BS*DD/4);
    cvt16_kernel<<<(DD*DD/4 + 255)/256, 256>>>(wq, w16,           DD*DD/4);
    cvt16_kernel<<<(DD*DD/4 + 255)/256, 256>>>(wk, w16 + DD*DD,   DD*DD/4);
    cvt16_kernel<<<(DD*DD/4 + 255)/256, 256>>>(wv, w16 + 2*DD*DD, DD*DD/4);
    cvt16_kernel<<<(DD*DD/4 + 255)/256, 256>>>(wo, wo16, DD*DD/4);

    // 2. fused QKV projection (fp16 2-pass) -> Q/K/V bf16 hi/lo
    gemm_fp16_kernel<<<dim3(BS/GM_BM, 3*DD/GM_BN), 256, GSMEM>>>(
        xh, xl, w16, nullptr, nullptr, 0);

    // 3. causal flash attention (bf16x3) -> ctx fp16 hi/lo
    flash_mma_kernel<<<dim3(SS/BR, BB*HH), 256, FSMEM>>>();

    // 4. output projection + bias (fp16 2-pass, fp32 out)
    gemm_fp16_kernel<<<dim3(BS/GM_BM, DD/GM_BN), 256, GSMEM>>>(
        ch, cl, wo16, out, wo_b, 1);
}

// round 6
// speedup vs baseline: 3.4892x; 1.0141x over previous
#include <cuda_runtime.h>
#include <cuda_bf16.h>
#include <cuda_fp16.h>
#include <cstdint>

// Problem constants
#define BB 4
#define SS 2048
#define DD 1024
#define HH 16
#define HD 64
#define BS (BB*SS)          // 8192

// ---------------------------------------------------------------------------
// Scratch (device globals; no allocation allowed)
// ---------------------------------------------------------------------------
__device__ __half g_xh16[BS*DD], g_xl16[BS*DD];             // x split (fp16 hi/lo)
__device__ __half g_w16[3*DD*DD];                           // fused Wq|Wk|Wv fp16
__device__ __half g_wo16[DD*DD];                            // Wo fp16
__device__ __half g_ch16[BS*DD], g_cl16[BS*DD];             // ctx split (fp16 hi/lo)

__device__ __nv_bfloat16 g_qh[BS*DD], g_ql[BS*DD];          // Q (scaled) bf16 hi/lo
__device__ __nv_bfloat16 g_kh[BS*DD], g_kl[BS*DD];
__device__ __nv_bfloat16 g_vh[BS*DD], g_vl[BS*DD];

// ---------------------------------------------------------------------------
// Portable (compute_103-safe) PTX helpers
// ---------------------------------------------------------------------------
__device__ __forceinline__ uint32_t smem_u32(const void* p) {
    uint32_t a;
    asm("{ .reg .u64 t; cvta.to.shared.u64 t, %1; cvt.u32.u64 %0, t; }" : "=r"(a) : "l"(p));
    return a;
}
__device__ __forceinline__ void cp16(uint32_t dst, const void* src) {
    asm volatile("cp.async.cg.shared.global [%0], [%1], 16;" :: "r"(dst), "l"(src) : "memory");
}
#define CP_COMMIT() asm volatile("cp.async.commit_group;" ::: "memory")
#define CP_WAIT0()  asm volatile("cp.async.wait_group 0;" ::: "memory")
#define CP_WAIT1()  asm volatile("cp.async.wait_group 1;" ::: "memory")
#define CP_WAIT2()  asm volatile("cp.async.wait_group 2;" ::: "memory")

__device__ __forceinline__ void ldsm4(uint32_t& r0, uint32_t& r1, uint32_t& r2, uint32_t& r3,
                                      uint32_t addr) {
    asm volatile("ldmatrix.sync.aligned.m8n8.x4.shared.b16 {%0,%1,%2,%3}, [%4];"
                 : "=r"(r0), "=r"(r1), "=r"(r2), "=r"(r3) : "r"(addr));
}
__device__ __forceinline__ void ldsm4t(uint32_t& r0, uint32_t& r1, uint32_t& r2, uint32_t& r3,
                                       uint32_t addr) {
    asm volatile("ldmatrix.sync.aligned.m8n8.x4.trans.shared.b16 {%0,%1,%2,%3}, [%4];"
                 : "=r"(r0), "=r"(r1), "=r"(r2), "=r"(r3) : "r"(addr));
}
// bf16 mma (flash)
__device__ __forceinline__ void mma16816(float* c,
                                         uint32_t a0, uint32_t a1, uint32_t a2, uint32_t a3,
                                         uint32_t b0, uint32_t b1) {
    asm volatile("mma.sync.aligned.m16n8k16.row.col.f32.bf16.bf16.f32 "
                 "{%0,%1,%2,%3}, {%4,%5,%6,%7}, {%8,%9}, {%0,%1,%2,%3};"
                 : "+f"(c[0]), "+f"(c[1]), "+f"(c[2]), "+f"(c[3])
                 : "r"(a0), "r"(a1), "r"(a2), "r"(a3), "r"(b0), "r"(b1));
}
// fp16 mma (GEMMs)
__device__ __forceinline__ void mma16816h(float* c,
                                          uint32_t a0, uint32_t a1, uint32_t a2, uint32_t a3,
                                          uint32_t b0, uint32_t b1) {
    asm volatile("mma.sync.aligned.m16n8k16.row.col.f32.f16.f16.f32 "
                 "{%0,%1,%2,%3}, {%4,%5,%6,%7}, {%8,%9}, {%0,%1,%2,%3};"
                 : "+f"(c[0]), "+f"(c[1]), "+f"(c[2]), "+f"(c[3])
                 : "r"(a0), "r"(a1), "r"(a2), "r"(a3), "r"(b0), "r"(b1));
}
__device__ __forceinline__ float ex2f(float x) {
    float y; asm("ex2.approx.f32 %0, %1;" : "=f"(y) : "f"(x)); return y;
}
__device__ __forceinline__ uint32_t packbf(float x, float y) {
    __nv_bfloat162 t = __floats2bfloat162_rn(x, y);
    return *(uint32_t*)&t;
}
__device__ __forceinline__ void hilo2(float v0, float v1, uint32_t& hw, uint32_t& lw) {
    __nv_bfloat16 h0 = __float2bfloat16(v0), h1 = __float2bfloat16(v1);
    __nv_bfloat162 hp = {h0, h1};
    hw = *(uint32_t*)&hp;
    lw = packbf(v0 - __bfloat162float(h0), v1 - __bfloat162float(h1));
}
__device__ __forceinline__ void hilo2h(float v0, float v1, uint32_t& hw, uint32_t& lw) {
    __half h0 = __float2half_rn(v0), h1 = __float2half_rn(v1);
    __half2 hp = {h0, h1};
    hw = *(uint32_t*)&hp;
    __half2 lp = __floats2half2_rn(v0 - __half2float(h0), v1 - __half2float(h1));
    lw = *(uint32_t*)&lp;
}

// ---------------------------------------------------------------------------
// fp32 -> fp16 hi/lo split (activations)
// ---------------------------------------------------------------------------
__global__ __launch_bounds__(256)
void split16_kernel(const float* __restrict__ src, __half* __restrict__ hi,
                    __half* __restrict__ lo, int n4)
{
    int i = blockIdx.x * 256 + threadIdx.x;
    if (i >= n4) return;
    float4 v = ((const float4*)src)[i];
    uint32_t h0, l0, h1, l1;
    hilo2h(v.x, v.y, h0, l0);
    hilo2h(v.z, v.w, h1, l1);
    ((uint32_t*)hi)[i*2+0] = h0;  ((uint32_t*)hi)[i*2+1] = h1;
    ((uint32_t*)lo)[i*2+0] = l0;  ((uint32_t*)lo)[i*2+1] = l1;
}

// fp32 -> fp16 convert (weights)
__global__ __launch_bounds__(256)
void cvt16_kernel(const float* __restrict__ src, __half* __restrict__ dst, int n4)
{
    int i = blockIdx.x * 256 + threadIdx.x;
    if (i >= n4) return;
    float4 v = ((const float4*)src)[i];
    __half2 p0 = __floats2half2_rn(v.x, v.y);
    __half2 p1 = __floats2half2_rn(v.z, v.w);
    ((uint32_t*)dst)[i*2+0] = *(uint32_t*)&p0;
    ((uint32_t*)dst)[i*2+1] = *(uint32_t*)&p1;
}

// ---------------------------------------------------------------------------
// fp16 2-pass GEMM via mma.sync: C = (Ah + Al) * B^T, B fp16 single.
// CTA 128x256, BK=32, 4-stage cp.async, 8 warps (2M x 4N), warp 64x64.
// mode 0: write Q/K/V as bf16 hi/lo (Q scaled 0.125*log2e); mode 1: fp32 + bias
// ---------------------------------------------------------------------------
#define GM_BM 128
#define GM_BN 256
#define GM_BK 32
#define GM_TILES 32            // K=1024 / 32
#define LSTR 40                // smem row stride in halves (80B)

#define TEN_A  10240u          // bytes per 128x32 fp16 tensor (LSTR-padded)
#define B_BYT  20480u          // 256x32 fp16 tensor
#define STG_B  40960u          // Ah + Al + B per stage
#define GSMEM  163840          // 4 stages

#define QSCALE 0.18033688011112042f   // (1/8) * log2(e)

__global__ __launch_bounds__(256, 1)
void gemm_fp16_kernel(const __half* __restrict__ Ah,
                      const __half* __restrict__ Al,
                      const __half* __restrict__ Bw,
                      float* __restrict__ outp,
                      const float* __restrict__ bias,
                      int mode)
{
    extern __shared__ char smem[];
    const uint32_t sb = smem_u32(smem);

    const int tid = threadIdx.x;
    const int lid = tid & 31;
    const int wid = tid >> 5;
    const int wm = wid >> 2;      // 0..1 (64 rows)
    const int wn = wid & 3;       // 0..3 (64 cols)

    const int m0 = blockIdx.x * GM_BM;
    const int n0 = blockIdx.y * GM_BN;

    float acc[4][8][4];
    #pragma unroll
    for (int i = 0; i < 4; i++)
        #pragma unroll
        for (int j = 0; j < 8; j++)
            #pragma unroll
            for (int c = 0; c < 4; c++) acc[i][j][c] = 0.f;

    auto load_tile = [&](int t) {
        const int k0 = t * GM_BK;
        const uint32_t base = sb + (uint32_t)(t & 3) * STG_B;
        #pragma unroll
        for (int it = 0; it < 2; it++) {
            int idx = tid + it * 256;  int r = idx >> 2, c = idx & 3;
            cp16(base + (uint32_t)(r * LSTR + c * 8) * 2,
                 Ah + (size_t)(m0 + r) * DD + k0 + c * 8);
        }
        #pragma unroll
        for (int it = 0; it < 2; it++) {
            int idx = tid + it * 256;  int r = idx >> 2, c = idx & 3;
            cp16(base + TEN_A + (uint32_t)(r * LSTR + c * 8) * 2,
                 Al + (size_t)(m0 + r) * DD + k0 + c * 8);
        }
        #pragma unroll
        for (int it = 0; it < 4; it++) {
            int idx = tid + it * 256;  int r = idx >> 2, c = idx & 3;
            cp16(base + 2 * TEN_A + (uint32_t)(r * LSTR + c * 8) * 2,
                 Bw + (size_t)(n0 + r) * DD + k0 + c * 8);
        }
        CP_COMMIT();
    };

    load_tile(0);
    load_tile(1);
    load_tile(2);

    const int q = lid >> 3;
    const int r = lid & 7;
    const int arow = r + (q & 1) * 8;
    const int acol = (q >> 1) * 8;
    const int brow = r + (q >> 1) * 8;
    const int bcol = (q & 1) * 8;

    for (int i = 0; i < GM_TILES; i++) {
        if (i + 2 < GM_TILES) { CP_WAIT2(); }
        else if (i + 1 < GM_TILES) { CP_WAIT1(); }
        else { CP_WAIT0(); }
        __syncthreads();
        if (i + 3 < GM_TILES) load_tile(i + 3);

        const uint32_t stg = sb + (uint32_t)(i & 3) * STG_B;

        #pragma unroll
        for (int kst = 0; kst < 2; kst++) {
            const int kb = kst * 16;
            uint32_t b[8][2];
            #pragma unroll
            for (int np = 0; np < 4; np++) {
                uint32_t addr = stg + 2 * TEN_A +
                    (uint32_t)((wn * 64 + np * 16 + brow) * LSTR + kb + bcol) * 2;
                ldsm4(b[2*np][0], b[2*np][1], b[2*np+1][0], b[2*np+1][1], addr);
            }
            uint32_t a[4][4];
            #pragma unroll
            for (int mt = 0; mt < 4; mt++) {
                uint32_t addr = stg +
                    (uint32_t)((wm * 64 + mt * 16 + arow) * LSTR + kb + acol) * 2;
                ldsm4(a[mt][0], a[mt][1], a[mt][2], a[mt][3], addr);
            }
            #pragma unroll
            for (int mt = 0; mt < 4; mt++)
                #pragma unroll
                for (int nt = 0; nt < 8; nt++)
                    mma16816h(acc[mt][nt], a[mt][0], a[mt][1], a[mt][2], a[mt][3],
                              b[nt][0], b[nt][1]);
            #pragma unroll
            for (int mt = 0; mt < 4; mt++) {
                uint32_t addr = stg + TEN_A +
                    (uint32_t)((wm * 64 + mt * 16 + arow) * LSTR + kb + acol) * 2;
                ldsm4(a[mt][0], a[mt][1], a[mt][2], a[mt][3], addr);
            }
            #pragma unroll
            for (int mt = 0; mt < 4; mt++)
                #pragma unroll
                for (int nt = 0; nt < 8; nt++)
                    mma16816h(acc[mt][nt], a[mt][0], a[mt][1], a[mt][2], a[mt][3],
                              b[nt][0], b[nt][1]);
        }
    }

    // Epilogue
    if (mode == 0) {
        const int sel = n0 >> 10;
        __nv_bfloat16* __restrict__ oph = (sel == 0) ? g_qh : (sel == 1) ? g_kh : g_vh;
        __nv_bfloat16* __restrict__ opl = (sel == 0) ? g_ql : (sel == 1) ? g_kl : g_vl;
        const float scale = (sel == 0) ? QSCALE : 1.0f;
        const int ncta = n0 & (DD - 1);
        #pragma unroll
        for (int mt = 0; mt < 4; mt++) {
            int row = m0 + wm * 64 + mt * 16 + (lid >> 2);
            #pragma unroll
            for (int nt = 0; nt < 8; nt++) {
                int col = ncta + wn * 64 + nt * 8 + (lid & 3) * 2;
                uint32_t hw, lw;
                hilo2(acc[mt][nt][0] * scale, acc[mt][nt][1] * scale, hw, lw);
                *(uint32_t*)&oph[(size_t)row * DD + col] = hw;
                *(uint32_t*)&opl[(size_t)row * DD + col] = lw;
                hilo2(acc[mt][nt][2] * scale, acc[mt][nt][3] * scale, hw, lw);
                *(uint32_t*)&oph[(size_t)(row + 8) * DD + col] = hw;
                *(uint32_t*)&opl[(size_t)(row + 8) * DD + col] = lw;
            }
        }
    } else {
        #pragma unroll
        for (int mt = 0; mt < 4; mt++) {
            int row = m0 + wm * 64 + mt * 16 + (lid >> 2);
            #pragma unroll
            for (int nt = 0; nt < 8; nt++) {
                int col = n0 + wn * 64 + nt * 8 + (lid & 3) * 2;
                float2 bb = *(const float2*)&bias[col];
                float2 v0 = {acc[mt][nt][0] + bb.x, acc[mt][nt][1] + bb.y};
                float2 v1 = {acc[mt][nt][2] + bb.x, acc[mt][nt][3] + bb.y};
                *(float2*)&outp[(size_t)row * DD + col] = v0;
                *(float2*)&outp[(size_t)(row + 8) * DD + col] = v1;
            }
        }
    }
}

// ---------------------------------------------------------------------------
// Flash attention (causal) on mma.sync, bf16x3 both products. (proven)
// ctx epilogue writes fp16 hi/lo for the oproj GEMM.
// ---------------------------------------------------------------------------
#define BR 128
#define BC 64
#define KSTR 72

#define FQ_OFF  0u
#define FST_OFF 36864u
#define FSTAGE  36864u
#define FTEN    9216u
#define FSMEM   110592

__global__ __launch_bounds__(256)
void flash_mma_kernel()
{
    extern __shared__ char smem[];
    const uint32_t sb = smem_u32(smem);

    const int tid = threadIdx.x;
    const int lid = tid & 31;
    const int wid = tid >> 5;
    const int itile = blockIdx.x;
    const int bh = blockIdx.y;
    const int b = bh >> 4, h = bh & 15;
    const int qbase = itile * BR;
    const int nkt = 2 * itile + 2;

    const size_t gq  = ((size_t)(b * SS + qbase)) * DD + h * HD;
    const size_t gkv = ((size_t)(b * SS)) * DD + h * HD;

    #pragma unroll
    for (int t = 0; t < 8; t++) {
        int idx = tid + t * 256;
        int ten = idx >> 10;
        int r = (idx >> 3) & 127;
        int c = idx & 7;
        const __nv_bfloat16* src = ten ? g_ql : g_qh;
        cp16(sb + FQ_OFF + (uint32_t)ten * (BR * KSTR * 2) + (uint32_t)(r * KSTR + c * 8) * 2,
             src + gq + (size_t)r * DD + c * 8);
    }
    CP_COMMIT();

    auto load_kv = [&](int kt) {
        const int buf = kt & 1;
        const uint32_t base = sb + FST_OFF + buf * FSTAGE;
        const size_t gk = gkv + (size_t)(kt * BC) * DD;
        #pragma unroll
        for (int t = 0; t < 8; t++) {
            int idx = tid + t * 256;
            int ten = idx >> 9;
            int r = (idx >> 3) & 63;
            int c = idx & 7;
            const __nv_bfloat16* src = (ten == 0) ? g_kh : (ten == 1) ? g_kl
                                     : (ten == 2) ? g_vh : g_vl;
            cp16(base + (uint32_t)ten * FTEN + (uint32_t)(r * KSTR + c * 8) * 2,
                 src + gk + (size_t)r * DD + c * 8);
        }
        CP_COMMIT();
    };

    load_kv(0);
    if (nkt > 1) load_kv(1);

    CP_WAIT2();
    __syncthreads();

    const int q4 = lid >> 3;
    const int r8 = lid & 7;
    const int arow = r8 + (q4 & 1) * 8;
    const int acol = (q4 >> 1) * 8;
    const int brow = r8 + (q4 >> 1) * 8;
    const int bcol = (q4 & 1) * 8;

    uint32_t qh[4][4], ql[4][4];
    #pragma unroll
    for (int ks = 0; ks < 4; ks++) {
        uint32_t ao = (uint32_t)((wid * 16 + arow) * KSTR + ks * 16 + acol) * 2;
        ldsm4(qh[ks][0], qh[ks][1], qh[ks][2], qh[ks][3], sb + FQ_OFF + ao);
        ldsm4(ql[ks][0], ql[ks][1], ql[ks][2], ql[ks][3], sb + FQ_OFF + BR * KSTR * 2 + ao);
    }

    float o[8][4];
    #pragma unroll
    for (int nf = 0; nf < 8; nf++)
        #pragma unroll
        for (int c = 0; c < 4; c++) o[nf][c] = 0.f;
    float m0 = -1e30f, m1 = -1e30f, ls0 = 0.f, ls1 = 0.f;

    const int rowg = qbase + wid * 16 + (lid >> 2);

    for (int kt = 0; kt < nkt; kt++) {
        const int buf = kt & 1;
        if (kt + 1 < nkt) { CP_WAIT1(); } else { CP_WAIT0(); }
        __syncthreads();

        const uint32_t kb = sb + FST_OFF + buf * FSTAGE;

        float s[8][4];
        #pragma unroll
        for (int nf = 0; nf < 8; nf++)
            #pragma unroll
            for (int c = 0; c < 4; c++) s[nf][c] = 0.f;

        #pragma unroll
        for (int ks = 0; ks < 4; ks++) {
            #pragma unroll
            for (int np = 0; np < 4; np++) {
                uint32_t ao = (uint32_t)((np * 16 + brow) * KSTR + ks * 16 + bcol) * 2;
                uint32_t k0, k1, k2, k3, l0, l1, l2, l3;
                ldsm4(k0, k1, k2, k3, kb + ao);
                ldsm4(l0, l1, l2, l3, kb + FTEN + ao);
                mma16816(s[2*np],   qh[ks][0], qh[ks][1], qh[ks][2], qh[ks][3], k0, k1);
                mma16816(s[2*np+1], qh[ks][0], qh[ks][1], qh[ks][2], qh[ks][3], k2, k3);
                mma16816(s[2*np],   ql[ks][0], ql[ks][1], ql[ks][2], ql[ks][3], k0, k1);
                mma16816(s[2*np+1], ql[ks][0], ql[ks][1], ql[ks][2], ql[ks][3], k2, k3);
                mma16816(s[2*np],   qh[ks][0], qh[ks][1], qh[ks][2], qh[ks][3], l0, l1);
                mma16816(s[2*np+1], qh[ks][0], qh[ks][1], qh[ks][2], qh[ks][3], l2, l3);
            }
        }

        if (kt >= nkt - 2) {
            const int colb = kt * BC + (lid & 3) * 2;
            #pragma unroll
            for (int nf = 0; nf < 8; nf++) {
                int c0 = colb + nf * 8;
                if (c0     > rowg)     s[nf][0] = -1e30f;
                if (c0 + 1 > rowg)     s[nf][1] = -1e30f;
                if (c0     > rowg + 8) s[nf][2] = -1e30f;
                if (c0 + 1 > rowg + 8) s[nf][3] = -1e30f;
            }
        }

        float mx0 = -1e30f, mx1 = -1e30f;
        #pragma unroll
        for (int nf = 0; nf < 8; nf++) {
            mx0 = fmaxf(mx0, fmaxf(s[nf][0], s[nf][1]));
            mx1 = fmaxf(mx1, fmaxf(s[nf][2], s[nf][3]));
        }
        mx0 = fmaxf(mx0, __shfl_xor_sync(0xffffffffu, mx0, 1));
        mx0 = fmaxf(mx0, __shfl_xor_sync(0xffffffffu, mx0, 2));
        mx1 = fmaxf(mx1, __shfl_xor_sync(0xffffffffu, mx1, 1));
        mx1 = fmaxf(mx1, __shfl_xor_sync(0xffffffffu, mx1, 2));
        const float nm0 = fmaxf(m0, mx0), nm1 = fmaxf(m1, mx1);
        const float al0 = ex2f(m0 - nm0), al1 = ex2f(m1 - nm1);
        m0 = nm0; m1 = nm1;
        ls0 *= al0; ls1 *= al1;

        #pragma unroll
        for (int nf = 0; nf < 8; nf++) {
            s[nf][0] = ex2f(s[nf][0] - m0);
            s[nf][1] = ex2f(s[nf][1] - m0);
            s[nf][2] = ex2f(s[nf][2] - m1);
            s[nf][3] = ex2f(s[nf][3] - m1);
            ls0 += s[nf][0] + s[nf][1];
            ls1 += s[nf][2] + s[nf][3];
        }
        #pragma unroll
        for (int nf = 0; nf < 8; nf++) {
            o[nf][0] *= al0; o[nf][1] *= al0;
            o[nf][2] *= al1; o[nf][3] *= al1;
        }

        const int vlane_r = lid & 15;
        const int vlane_c = (lid >> 4) * 8;
        #pragma unroll
        for (int ks = 0; ks < 4; ks++) {
            uint32_t pa[4], pb[4];
            {
                hilo2(s[2*ks][0],   s[2*ks][1],   pa[0], pb[0]);
                hilo2(s[2*ks][2],   s[2*ks][3],   pa[1], pb[1]);
                hilo2(s[2*ks+1][0], s[2*ks+1][1], pa[2], pb[2]);
                hilo2(s[2*ks+1][2], s[2*ks+1][3], pa[3], pb[3]);
            }
            #pragma unroll
            for (int np = 0; np < 4; np++) {
                uint32_t ao = (uint32_t)((ks * 16 + vlane_r) * KSTR + np * 16 + vlane_c) * 2;
                uint32_t v0, v1, v2, v3, w0, w1, w2, w3;
                ldsm4t(v0, v1, v2, v3, kb + 2 * FTEN + ao);
                ldsm4t(w0, w1, w2, w3, kb + 3 * FTEN + ao);
                mma16816(o[2*np],   pa[0], pa[1], pa[2], pa[3], v0, v1);
                mma16816(o[2*np+1], pa[0], pa[1], pa[2], pa[3], v2, v3);
                mma16816(o[2*np],   pb[0], pb[1], pb[2], pb[3], v0, v1);
                mma16816(o[2*np+1], pb[0], pb[1], pb[2], pb[3], v2, v3);
                mma16816(o[2*np],   pa[0], pa[1], pa[2], pa[3], w0, w1);
                mma16816(o[2*np+1], pa[0], pa[1], pa[2], pa[3], w2, w3);
            }
        }

        __syncthreads();
        if (kt + 2 < nkt) load_kv(kt + 2);
    }

    ls0 += __shfl_xor_sync(0xffffffffu, ls0, 1);
    ls0 += __shfl_xor_sync(0xffffffffu, ls0, 2);
    ls1 += __shfl_xor_sync(0xffffffffu, ls1, 1);
    ls1 += __shfl_xor_sync(0xffffffffu, ls1, 2);
    const float li0 = 1.0f / ls0, li1 = 1.0f / ls1;

    const size_t row0 = (size_t)(b * SS + rowg);
    const int colb = h * HD + (lid & 3) * 2;
    #pragma unroll
    for (int nf = 0; nf < 8; nf++) {
        int col = colb + nf * 8;
        uint32_t hw, lw;
        hilo2h(o[nf][0] * li0, o[nf][1] * li0, hw, lw);
        *(uint32_t*)&g_ch16[row0 * DD + col] = hw;
        *(uint32_t*)&g_cl16[row0 * DD + col] = lw;
        hilo2h(o[nf][2] * li1, o[nf][3] * li1, hw, lw);
        *(uint32_t*)&g_ch16[(row0 + 8) * DD + col] = hw;
        *(uint32_t*)&g_cl16[(row0 + 8) * DD + col] = lw;
    }
}

// ---------------------------------------------------------------------------

extern "C" void kernel_launch(void* const* d_in, const int* in_sizes, int n_in,
                              void* d_out, int out_size)
{
    const float* x    = (const float*)d_in[0];
    const float* wq   = (const float*)d_in[1];
    const float* wk   = (const float*)d_in[2];
    const float* wv   = (const float*)d_in[3];
    const float* wo   = (const float*)d_in[4];
    const float* wo_b = (const float*)d_in[5];
    float* out = (float*)d_out;

    static int attr_done = 0;
    if (!attr_done) {
        cudaFuncSetAttribute(flash_mma_kernel,
                             cudaFuncAttributeMaxDynamicSharedMemorySize, FSMEM);
        cudaFuncSetAttribute(gemm_fp16_kernel,
                             cudaFuncAttributeMaxDynamicSharedMemorySize, GSMEM);
        attr_done = 1;
    }

    __half *xh, *xl, *w16, *wo16, *ch, *cl;
    cudaGetSymbolAddress((void**)&xh,   g_xh16);
    cudaGetSymbolAddress((void**)&xl,   g_xl16);
    cudaGetSymbolAddress((void**)&w16,  g_w16);
    cudaGetSymbolAddress((void**)&wo16, g_wo16);
    cudaGetSymbolAddress((void**)&ch,   g_ch16);
    cudaGetSymbolAddress((void**)&cl,   g_cl16);

    // 1. split x (fp16 hi/lo); convert weights to fp16
    split16_kernel<<<(BS*DD/4 + 255)/256, 256>>>(x, xh, xl, BS*DD/4);
    cvt16_kernel<<<(DD*DD/4 + 255)/256, 256>>>(wq, w16,           DD*DD/4);
    cvt16_kernel<<<(DD*DD/4 + 255)/256, 256>>>(wk, w16 + DD*DD,   DD*DD/4);
    cvt16_kernel<<<(DD*DD/4 + 255)/256, 256>>>(wv, w16 + 2*DD*DD, DD*DD/4);
    cvt16_kernel<<<(DD*DD/4 + 255)/256, 256>>>(wo, wo16, DD*DD/4);

    // 2. fused QKV projection (fp16 2-pass, 64x64 warp tiles) -> Q/K/V bf16 hi/lo
    gemm_fp16_kernel<<<dim3(BS/GM_BM, 3*DD/GM_BN), 256, GSMEM>>>(
        xh, xl, w16, nullptr, nullptr, 0);

    // 3. causal flash attention (bf16x3) -> ctx fp16 hi/lo
    flash_mma_kernel<<<dim3(SS/BR, BB*HH), 256, FSMEM>>>();

    // 4. output projection + bias (fp16 2-pass, fp32 out)
    gemm_fp16_kernel<<<dim3(BS/GM_BM, DD/GM_BN), 256, GSMEM>>>(
        ch, cl, wo16, out, wo_b, 1);
}

// round 7
// speedup vs baseline: 4.3355x; 1.2426x over previous
#include <cuda_runtime.h>
#include <cuda_bf16.h>
#include <cuda_fp16.h>
#include <cstdint>

// Problem constants
#define BB 4
#define SS 2048
#define DD 1024
#define HH 16
#define HD 64
#define BS (BB*SS)          // 8192

// ---------------------------------------------------------------------------
// Scratch (device globals; no allocation allowed)
// ---------------------------------------------------------------------------
__device__ __half g_x16[BS*DD];                             // x fp16
__device__ __half g_w16[3*DD*DD];                           // fused Wq|Wk|Wv fp16
__device__ __half g_wo16[DD*DD];                            // Wo fp16
__device__ __half g_c16[BS*DD];                             // ctx fp16

__device__ __nv_bfloat16 g_qh[BS*DD], g_ql[BS*DD];          // Q (scaled) bf16 hi/lo
__device__ __nv_bfloat16 g_kh[BS*DD], g_kl[BS*DD];
__device__ __nv_bfloat16 g_vh[BS*DD], g_vl[BS*DD];

// ---------------------------------------------------------------------------
// Portable (compute_103-safe) PTX helpers
// ---------------------------------------------------------------------------
__device__ __forceinline__ uint32_t smem_u32(const void* p) {
    uint32_t a;
    asm("{ .reg .u64 t; cvta.to.shared.u64 t, %1; cvt.u32.u64 %0, t; }" : "=r"(a) : "l"(p));
    return a;
}
__device__ __forceinline__ void cp16(uint32_t dst, const void* src) {
    asm volatile("cp.async.cg.shared.global [%0], [%1], 16;" :: "r"(dst), "l"(src) : "memory");
}
#define CP_COMMIT() asm volatile("cp.async.commit_group;" ::: "memory")
#define CP_WAIT0()  asm volatile("cp.async.wait_group 0;" ::: "memory")
#define CP_WAIT1()  asm volatile("cp.async.wait_group 1;" ::: "memory")
#define CP_WAIT2()  asm volatile("cp.async.wait_group 2;" ::: "memory")

__device__ __forceinline__ void ldsm4(uint32_t& r0, uint32_t& r1, uint32_t& r2, uint32_t& r3,
                                      uint32_t addr) {
    asm volatile("ldmatrix.sync.aligned.m8n8.x4.shared.b16 {%0,%1,%2,%3}, [%4];"
                 : "=r"(r0), "=r"(r1), "=r"(r2), "=r"(r3) : "r"(addr));
}
__device__ __forceinline__ void ldsm4t(uint32_t& r0, uint32_t& r1, uint32_t& r2, uint32_t& r3,
                                       uint32_t addr) {
    asm volatile("ldmatrix.sync.aligned.m8n8.x4.trans.shared.b16 {%0,%1,%2,%3}, [%4];"
                 : "=r"(r0), "=r"(r1), "=r"(r2), "=r"(r3) : "r"(addr));
}
// bf16 mma (flash)
__device__ __forceinline__ void mma16816(float* c,
                                         uint32_t a0, uint32_t a1, uint32_t a2, uint32_t a3,
                                         uint32_t b0, uint32_t b1) {
    asm volatile("mma.sync.aligned.m16n8k16.row.col.f32.bf16.bf16.f32 "
                 "{%0,%1,%2,%3}, {%4,%5,%6,%7}, {%8,%9}, {%0,%1,%2,%3};"
                 : "+f"(c[0]), "+f"(c[1]), "+f"(c[2]), "+f"(c[3])
                 : "r"(a0), "r"(a1), "r"(a2), "r"(a3), "r"(b0), "r"(b1));
}
// fp16 mma (GEMMs)
__device__ __forceinline__ void mma16816h(float* c,
                                          uint32_t a0, uint32_t a1, uint32_t a2, uint32_t a3,
                                          uint32_t b0, uint32_t b1) {
    asm volatile("mma.sync.aligned.m16n8k16.row.col.f32.f16.f16.f32 "
                 "{%0,%1,%2,%3}, {%4,%5,%6,%7}, {%8,%9}, {%0,%1,%2,%3};"
                 : "+f"(c[0]), "+f"(c[1]), "+f"(c[2]), "+f"(c[3])
                 : "r"(a0), "r"(a1), "r"(a2), "r"(a3), "r"(b0), "r"(b1));
}
__device__ __forceinline__ float ex2f(float x) {
    float y; asm("ex2.approx.f32 %0, %1;" : "=f"(y) : "f"(x)); return y;
}
__device__ __forceinline__ uint32_t packbf(float x, float y) {
    __nv_bfloat162 t = __floats2bfloat162_rn(x, y);
    return *(uint32_t*)&t;
}
__device__ __forceinline__ void hilo2(float v0, float v1, uint32_t& hw, uint32_t& lw) {
    __nv_bfloat16 h0 = __float2bfloat16(v0), h1 = __float2bfloat16(v1);
    __nv_bfloat162 hp = {h0, h1};
    hw = *(uint32_t*)&hp;
    lw = packbf(v0 - __bfloat162float(h0), v1 - __bfloat162float(h1));
}

// fp32 -> fp16 convert
__global__ __launch_bounds__(256)
void cvt16_kernel(const float* __restrict__ src, __half* __restrict__ dst, int n4)
{
    int i = blockIdx.x * 256 + threadIdx.x;
    if (i >= n4) return;
    float4 v = ((const float4*)src)[i];
    __half2 p0 = __floats2half2_rn(v.x, v.y);
    __half2 p1 = __floats2half2_rn(v.z, v.w);
    ((uint32_t*)dst)[i*2+0] = *(uint32_t*)&p0;
    ((uint32_t*)dst)[i*2+1] = *(uint32_t*)&p1;
}

// ---------------------------------------------------------------------------
// fp16 single-pass GEMM via mma.sync: C = A * B^T.
// CTA 128x256, BK=32, 4-stage cp.async, 8 warps (2M x 4N), warp 64x64.
// mode 0: write Q/K/V as bf16 hi/lo (Q scaled 0.125*log2e); mode 1: fp32 + bias
// ---------------------------------------------------------------------------
#define GM_BM 128
#define GM_BN 256
#define GM_BK 32
#define GM_TILES 32            // K=1024 / 32
#define LSTR 40                // smem row stride in halves (80B)

#define TEN_A  10240u          // 128x32 fp16 tensor (LSTR-padded)
#define STG_B  30720u          // A + B per stage
#define GSMEM  122880          // 4 stages

#define QSCALE 0.18033688011112042f   // (1/8) * log2(e)

__global__ __launch_bounds__(256, 1)
void gemm_fp16_kernel(const __half* __restrict__ Aa,
                      const __half* __restrict__ Bw,
                      float* __restrict__ outp,
                      const float* __restrict__ bias,
                      int mode)
{
    extern __shared__ char smem[];
    const uint32_t sb = smem_u32(smem);

    const int tid = threadIdx.x;
    const int lid = tid & 31;
    const int wid = tid >> 5;
    const int wm = wid >> 2;      // 0..1 (64 rows)
    const int wn = wid & 3;       // 0..3 (64 cols)

    const int m0 = blockIdx.x * GM_BM;
    const int n0 = blockIdx.y * GM_BN;

    float acc[4][8][4];
    #pragma unroll
    for (int i = 0; i < 4; i++)
        #pragma unroll
        for (int j = 0; j < 8; j++)
            #pragma unroll
            for (int c = 0; c < 4; c++) acc[i][j][c] = 0.f;

    auto load_tile = [&](int t) {
        const int k0 = t * GM_BK;
        const uint32_t base = sb + (uint32_t)(t & 3) * STG_B;
        #pragma unroll
        for (int it = 0; it < 2; it++) {
            int idx = tid + it * 256;  int r = idx >> 2, c = idx & 3;
            cp16(base + (uint32_t)(r * LSTR + c * 8) * 2,
                 Aa + (size_t)(m0 + r) * DD + k0 + c * 8);
        }
        #pragma unroll
        for (int it = 0; it < 4; it++) {
            int idx = tid + it * 256;  int r = idx >> 2, c = idx & 3;
            cp16(base + TEN_A + (uint32_t)(r * LSTR + c * 8) * 2,
                 Bw + (size_t)(n0 + r) * DD + k0 + c * 8);
        }
        CP_COMMIT();
    };

    load_tile(0);
    load_tile(1);
    load_tile(2);

    const int q = lid >> 3;
    const int r = lid & 7;
    const int arow = r + (q & 1) * 8;
    const int acol = (q >> 1) * 8;
    const int brow = r + (q >> 1) * 8;
    const int bcol = (q & 1) * 8;

    for (int i = 0; i < GM_TILES; i++) {
        if (i + 2 < GM_TILES) { CP_WAIT2(); }
        else if (i + 1 < GM_TILES) { CP_WAIT1(); }
        else { CP_WAIT0(); }
        __syncthreads();
        if (i + 3 < GM_TILES) load_tile(i + 3);

        const uint32_t stg = sb + (uint32_t)(i & 3) * STG_B;

        #pragma unroll
        for (int kst = 0; kst < 2; kst++) {
            const int kb = kst * 16;
            uint32_t b[8][2];
            #pragma unroll
            for (int np = 0; np < 4; np++) {
                uint32_t addr = stg + TEN_A +
                    (uint32_t)((wn * 64 + np * 16 + brow) * LSTR + kb + bcol) * 2;
                ldsm4(b[2*np][0], b[2*np][1], b[2*np+1][0], b[2*np+1][1], addr);
            }
            uint32_t a[4][4];
            #pragma unroll
            for (int mt = 0; mt < 4; mt++) {
                uint32_t addr = stg +
                    (uint32_t)((wm * 64 + mt * 16 + arow) * LSTR + kb + acol) * 2;
                ldsm4(a[mt][0], a[mt][1], a[mt][2], a[mt][3], addr);
            }
            #pragma unroll
            for (int mt = 0; mt < 4; mt++)
                #pragma unroll
                for (int nt = 0; nt < 8; nt++)
                    mma16816h(acc[mt][nt], a[mt][0], a[mt][1], a[mt][2], a[mt][3],
                              b[nt][0], b[nt][1]);
        }
    }

    // Epilogue
    if (mode == 0) {
        const int sel = n0 >> 10;
        __nv_bfloat16* __restrict__ oph = (sel == 0) ? g_qh : (sel == 1) ? g_kh : g_vh;
        __nv_bfloat16* __restrict__ opl = (sel == 0) ? g_ql : (sel == 1) ? g_kl : g_vl;
        const float scale = (sel == 0) ? QSCALE : 1.0f;
        const int ncta = n0 & (DD - 1);
        #pragma unroll
        for (int mt = 0; mt < 4; mt++) {
            int row = m0 + wm * 64 + mt * 16 + (lid >> 2);
            #pragma unroll
            for (int nt = 0; nt < 8; nt++) {
                int col = ncta + wn * 64 + nt * 8 + (lid & 3) * 2;
                uint32_t hw, lw;
                hilo2(acc[mt][nt][0] * scale, acc[mt][nt][1] * scale, hw, lw);
                *(uint32_t*)&oph[(size_t)row * DD + col] = hw;
                *(uint32_t*)&opl[(size_t)row * DD + col] = lw;
                hilo2(acc[mt][nt][2] * scale, acc[mt][nt][3] * scale, hw, lw);
                *(uint32_t*)&oph[(size_t)(row + 8) * DD + col] = hw;
                *(uint32_t*)&opl[(size_t)(row + 8) * DD + col] = lw;
            }
        }
    } else {
        #pragma unroll
        for (int mt = 0; mt < 4; mt++) {
            int row = m0 + wm * 64 + mt * 16 + (lid >> 2);
            #pragma unroll
            for (int nt = 0; nt < 8; nt++) {
                int col = n0 + wn * 64 + nt * 8 + (lid & 3) * 2;
                float2 bb = *(const float2*)&bias[col];
                float2 v0 = {acc[mt][nt][0] + bb.x, acc[mt][nt][1] + bb.y};
                float2 v1 = {acc[mt][nt][2] + bb.x, acc[mt][nt][3] + bb.y};
                *(float2*)&outp[(size_t)row * DD + col] = v0;
                *(float2*)&outp[(size_t)(row + 8) * DD + col] = v1;
            }
        }
    }
}

// ---------------------------------------------------------------------------
// Flash attention (causal) on mma.sync, bf16x3 both products. (proven)
// ctx epilogue writes single fp16 for the oproj GEMM.
// ---------------------------------------------------------------------------
#define BR 128
#define BC 64
#define KSTR 72

#define FQ_OFF  0u
#define FST_OFF 36864u
#define FSTAGE  36864u
#define FTEN    9216u
#define FSMEM   110592

__global__ __launch_bounds__(256)
void flash_mma_kernel()
{
    extern __shared__ char smem[];
    const uint32_t sb = smem_u32(smem);

    const int tid = threadIdx.x;
    const int lid = tid & 31;
    const int wid = tid >> 5;
    const int itile = blockIdx.x;
    const int bh = blockIdx.y;
    const int b = bh >> 4, h = bh & 15;
    const int qbase = itile * BR;
    const int nkt = 2 * itile + 2;

    const size_t gq  = ((size_t)(b * SS + qbase)) * DD + h * HD;
    const size_t gkv = ((size_t)(b * SS)) * DD + h * HD;

    #pragma unroll
    for (int t = 0; t < 8; t++) {
        int idx = tid + t * 256;
        int ten = idx >> 10;
        int r = (idx >> 3) & 127;
        int c = idx & 7;
        const __nv_bfloat16* src = ten ? g_ql : g_qh;
        cp16(sb + FQ_OFF + (uint32_t)ten * (BR * KSTR * 2) + (uint32_t)(r * KSTR + c * 8) * 2,
             src + gq + (size_t)r * DD + c * 8);
    }
    CP_COMMIT();

    auto load_kv = [&](int kt) {
        const int buf = kt & 1;
        const uint32_t base = sb + FST_OFF + buf * FSTAGE;
        const size_t gk = gkv + (size_t)(kt * BC) * DD;
        #pragma unroll
        for (int t = 0; t < 8; t++) {
            int idx = tid + t * 256;
            int ten = idx >> 9;
            int r = (idx >> 3) & 63;
            int c = idx & 7;
            const __nv_bfloat16* src = (ten == 0) ? g_kh : (ten == 1) ? g_kl
                                     : (ten == 2) ? g_vh : g_vl;
            cp16(base + (uint32_t)ten * FTEN + (uint32_t)(r * KSTR + c * 8) * 2,
                 src + gk + (size_t)r * DD + c * 8);
        }
        CP_COMMIT();
    };

    load_kv(0);
    if (nkt > 1) load_kv(1);

    CP_WAIT2();
    __syncthreads();

    const int q4 = lid >> 3;
    const int r8 = lid & 7;
    const int arow = r8 + (q4 & 1) * 8;
    const int acol = (q4 >> 1) * 8;
    const int brow = r8 + (q4 >> 1) * 8;
    const int bcol = (q4 & 1) * 8;

    uint32_t qh[4][4], ql[4][4];
    #pragma unroll
    for (int ks = 0; ks < 4; ks++) {
        uint32_t ao = (uint32_t)((wid * 16 + arow) * KSTR + ks * 16 + acol) * 2;
        ldsm4(qh[ks][0], qh[ks][1], qh[ks][2], qh[ks][3], sb + FQ_OFF + ao);
        ldsm4(ql[ks][0], ql[ks][1], ql[ks][2], ql[ks][3], sb + FQ_OFF + BR * KSTR * 2 + ao);
    }

    float o[8][4];
    #pragma unroll
    for (int nf = 0; nf < 8; nf++)
        #pragma unroll
        for (int c = 0; c < 4; c++) o[nf][c] = 0.f;
    float m0 = -1e30f, m1 = -1e30f, ls0 = 0.f, ls1 = 0.f;

    const int rowg = qbase + wid * 16 + (lid >> 2);

    for (int kt = 0; kt < nkt; kt++) {
        const int buf = kt & 1;
        if (kt + 1 < nkt) { CP_WAIT1(); } else { CP_WAIT0(); }
        __syncthreads();

        const uint32_t kb = sb + FST_OFF + buf * FSTAGE;

        float s[8][4];
        #pragma unroll
        for (int nf = 0; nf < 8; nf++)
            #pragma unroll
            for (int c = 0; c < 4; c++) s[nf][c] = 0.f;

        #pragma unroll
        for (int ks = 0; ks < 4; ks++) {
            #pragma unroll
            for (int np = 0; np < 4; np++) {
                uint32_t ao = (uint32_t)((np * 16 + brow) * KSTR + ks * 16 + bcol) * 2;
                uint32_t k0, k1, k2, k3, l0, l1, l2, l3;
                ldsm4(k0, k1, k2, k3, kb + ao);
                ldsm4(l0, l1, l2, l3, kb + FTEN + ao);
                mma16816(s[2*np],   qh[ks][0], qh[ks][1], qh[ks][2], qh[ks][3], k0, k1);
                mma16816(s[2*np+1], qh[ks][0], qh[ks][1], qh[ks][2], qh[ks][3], k2, k3);
                mma16816(s[2*np],   ql[ks][0], ql[ks][1], ql[ks][2], ql[ks][3], k0, k1);
                mma16816(s[2*np+1], ql[ks][0], ql[ks][1], ql[ks][2], ql[ks][3], k2, k3);
                mma16816(s[2*np],   qh[ks][0], qh[ks][1], qh[ks][2], qh[ks][3], l0, l1);
                mma16816(s[2*np+1], qh[ks][0], qh[ks][1], qh[ks][2], qh[ks][3], l2, l3);
            }
        }

        if (kt >= nkt - 2) {
            const int colb = kt * BC + (lid & 3) * 2;
            #pragma unroll
            for (int nf = 0; nf < 8; nf++) {
                int c0 = colb + nf * 8;
                if (c0     > rowg)     s[nf][0] = -1e30f;
                if (c0 + 1 > rowg)     s[nf][1] = -1e30f;
                if (c0     > rowg + 8) s[nf][2] = -1e30f;
                if (c0 + 1 > rowg + 8) s[nf][3] = -1e30f;
            }
        }

        float mx0 = -1e30f, mx1 = -1e30f;
        #pragma unroll
        for (int nf = 0; nf < 8; nf++) {
            mx0 = fmaxf(mx0, fmaxf(s[nf][0], s[nf][1]));
            mx1 = fmaxf(mx1, fmaxf(s[nf][2], s[nf][3]));
        }
        mx0 = fmaxf(mx0, __shfl_xor_sync(0xffffffffu, mx0, 1));
        mx0 = fmaxf(mx0, __shfl_xor_sync(0xffffffffu, mx0, 2));
        mx1 = fmaxf(mx1, __shfl_xor_sync(0xffffffffu, mx1, 1));
        mx1 = fmaxf(mx1, __shfl_xor_sync(0xffffffffu, mx1, 2));
        const float nm0 = fmaxf(m0, mx0), nm1 = fmaxf(m1, mx1);
        const float al0 = ex2f(m0 - nm0), al1 = ex2f(m1 - nm1);
        m0 = nm0; m1 = nm1;
        ls0 *= al0; ls1 *= al1;

        #pragma unroll
        for (int nf = 0; nf < 8; nf++) {
            s[nf][0] = ex2f(s[nf][0] - m0);
            s[nf][1] = ex2f(s[nf][1] - m0);
            s[nf][2] = ex2f(s[nf][2] - m1);
            s[nf][3] = ex2f(s[nf][3] - m1);
            ls0 += s[nf][0] + s[nf][1];
            ls1 += s[nf][2] + s[nf][3];
        }
        #pragma unroll
        for (int nf = 0; nf < 8; nf++) {
            o[nf][0] *= al0; o[nf][1] *= al0;
            o[nf][2] *= al1; o[nf][3] *= al1;
        }

        const int vlane_r = lid & 15;
        const int vlane_c = (lid >> 4) * 8;
        #pragma unroll
        for (int ks = 0; ks < 4; ks++) {
            uint32_t pa[4], pb[4];
            {
                hilo2(s[2*ks][0],   s[2*ks][1],   pa[0], pb[0]);
                hilo2(s[2*ks][2],   s[2*ks][3],   pa[1], pb[1]);
                hilo2(s[2*ks+1][0], s[2*ks+1][1], pa[2], pb[2]);
                hilo2(s[2*ks+1][2], s[2*ks+1][3], pa[3], pb[3]);
            }
            #pragma unroll
            for (int np = 0; np < 4; np++) {
                uint32_t ao = (uint32_t)((ks * 16 + vlane_r) * KSTR + np * 16 + vlane_c) * 2;
                uint32_t v0, v1, v2, v3, w0, w1, w2, w3;
                ldsm4t(v0, v1, v2, v3, kb + 2 * FTEN + ao);
                ldsm4t(w0, w1, w2, w3, kb + 3 * FTEN + ao);
                mma16816(o[2*np],   pa[0], pa[1], pa[2], pa[3], v0, v1);
                mma16816(o[2*np+1], pa[0], pa[1], pa[2], pa[3], v2, v3);
                mma16816(o[2*np],   pb[0], pb[1], pb[2], pb[3], v0, v1);
                mma16816(o[2*np+1], pb[0], pb[1], pb[2], pb[3], v2, v3);
                mma16816(o[2*np],   pa[0], pa[1], pa[2], pa[3], w0, w1);
                mma16816(o[2*np+1], pa[0], pa[1], pa[2], pa[3], w2, w3);
            }
        }

        __syncthreads();
        if (kt + 2 < nkt) load_kv(kt + 2);
    }

    ls0 += __shfl_xor_sync(0xffffffffu, ls0, 1);
    ls0 += __shfl_xor_sync(0xffffffffu, ls0, 2);
    ls1 += __shfl_xor_sync(0xffffffffu, ls1, 1);
    ls1 += __shfl_xor_sync(0xffffffffu, ls1, 2);
    const float li0 = 1.0f / ls0, li1 = 1.0f / ls1;

    const size_t row0 = (size_t)(b * SS + rowg);
    const int colb = h * HD + (lid & 3) * 2;
    #pragma unroll
    for (int nf = 0; nf < 8; nf++) {
        int col = colb + nf * 8;
        __half2 h0 = __floats2half2_rn(o[nf][0] * li0, o[nf][1] * li0);
        __half2 h1 = __floats2half2_rn(o[nf][2] * li1, o[nf][3] * li1);
        *(uint32_t*)&g_c16[row0 * DD + col] = *(uint32_t*)&h0;
        *(uint32_t*)&g_c16[(row0 + 8) * DD + col] = *(uint32_t*)&h1;
    }
}

// ---------------------------------------------------------------------------

extern "C" void kernel_launch(void* const* d_in, const int* in_sizes, int n_in,
                              void* d_out, int out_size)
{
    const float* x    = (const float*)d_in[0];
    const float* wq   = (const float*)d_in[1];
    const float* wk   = (const float*)d_in[2];
    const float* wv   = (const float*)d_in[3];
    const float* wo   = (const float*)d_in[4];
    const float* wo_b = (const float*)d_in[5];
    float* out = (float*)d_out;

    static int attr_done = 0;
    if (!attr_done) {
        cudaFuncSetAttribute(flash_mma_kernel,
                             cudaFuncAttributeMaxDynamicSharedMemorySize, FSMEM);
        cudaFuncSetAttribute(gemm_fp16_kernel,
                             cudaFuncAttributeMaxDynamicSharedMemorySize, GSMEM);
        attr_done = 1;
    }

    __half *x16, *w16, *wo16, *c16;
    cudaGetSymbolAddress((void**)&x16,  g_x16);
    cudaGetSymbolAddress((void**)&w16,  g_w16);
    cudaGetSymbolAddress((void**)&wo16, g_wo16);
    cudaGetSymbolAddress((void**)&c16,  g_c16);

    // 1. convert x and weights to fp16
    cvt16_kernel<<<(BS*DD/4 + 255)/256, 256>>>(x, x16, BS*DD/4);
    cvt16_kernel<<<(DD*DD/4 + 255)/256, 256>>>(wq, w16,           DD*DD/4);
    cvt16_kernel<<<(DD*DD/4 + 255)/256, 256>>>(wk, w16 + DD*DD,   DD*DD/4);
    cvt16_kernel<<<(DD*DD/4 + 255)/256, 256>>>(wv, w16 + 2*DD*DD, DD*DD/4);
    cvt16_kernel<<<(DD*DD/4 + 255)/256, 256>>>(wo, wo16, DD*DD/4);

    // 2. fused QKV projection (fp16 1-pass) -> Q/K/V bf16 hi/lo
    gemm_fp16_kernel<<<dim3(BS/GM_BM, 3*DD/GM_BN), 256, GSMEM>>>(
        x16, w16, nullptr, nullptr, 0);

    // 3. causal flash attention (bf16x3) -> ctx fp16
    flash_mma_kernel<<<dim3(SS/BR, BB*HH), 256, FSMEM>>>();

    // 4. output projection + bias (fp16 1-pass, fp32 out)
    gemm_fp16_kernel<<<dim3(BS/GM_BM, DD/GM_BN), 256, GSMEM>>>(
        c16, wo16, out, wo_b, 1);
}

// round 8
// speedup vs baseline: 6.0037x; 1.3848x over previous
#include <cuda_runtime.h>
#include <cuda_bf16.h>
#include <cuda_fp16.h>
#include <cstdint>

// Problem constants
#define BB 4
#define SS 2048
#define DD 1024
#define HH 16
#define HD 64
#define BS (BB*SS)          // 8192

// ---------------------------------------------------------------------------
// Scratch (device globals; no allocation allowed)
// ---------------------------------------------------------------------------
__device__ __half g_x16[BS*DD];                             // x fp16
__device__ __half g_w16[3*DD*DD];                           // fused Wq|Wk|Wv fp16
__device__ __half g_wo16[DD*DD];                            // Wo fp16
__device__ __half g_c16[BS*DD];                             // ctx fp16

__device__ __half g_q16h[BS*DD], g_q16l[BS*DD];             // Q (scaled) fp16 hi/lo
__device__ __half g_k16[BS*DD];                             // K fp16
__device__ __half g_v16[BS*DD];                             // V fp16

// ---------------------------------------------------------------------------
// Portable (compute_103-safe) PTX helpers
// ---------------------------------------------------------------------------
__device__ __forceinline__ uint32_t smem_u32(const void* p) {
    uint32_t a;
    asm("{ .reg .u64 t; cvta.to.shared.u64 t, %1; cvt.u32.u64 %0, t; }" : "=r"(a) : "l"(p));
    return a;
}
__device__ __forceinline__ void cp16(uint32_t dst, const void* src) {
    asm volatile("cp.async.cg.shared.global [%0], [%1], 16;" :: "r"(dst), "l"(src) : "memory");
}
#define CP_COMMIT() asm volatile("cp.async.commit_group;" ::: "memory")
#define CP_WAIT0()  asm volatile("cp.async.wait_group 0;" ::: "memory")
#define CP_WAIT1()  asm volatile("cp.async.wait_group 1;" ::: "memory")
#define CP_WAIT2()  asm volatile("cp.async.wait_group 2;" ::: "memory")

__device__ __forceinline__ void ldsm4(uint32_t& r0, uint32_t& r1, uint32_t& r2, uint32_t& r3,
                                      uint32_t addr) {
    asm volatile("ldmatrix.sync.aligned.m8n8.x4.shared.b16 {%0,%1,%2,%3}, [%4];"
                 : "=r"(r0), "=r"(r1), "=r"(r2), "=r"(r3) : "r"(addr));
}
__device__ __forceinline__ void ldsm4t(uint32_t& r0, uint32_t& r1, uint32_t& r2, uint32_t& r3,
                                       uint32_t addr) {
    asm volatile("ldmatrix.sync.aligned.m8n8.x4.trans.shared.b16 {%0,%1,%2,%3}, [%4];"
                 : "=r"(r0), "=r"(r1), "=r"(r2), "=r"(r3) : "r"(addr));
}
// fp16 mma
__device__ __forceinline__ void mma16816h(float* c,
                                          uint32_t a0, uint32_t a1, uint32_t a2, uint32_t a3,
                                          uint32_t b0, uint32_t b1) {
    asm volatile("mma.sync.aligned.m16n8k16.row.col.f32.f16.f16.f32 "
                 "{%0,%1,%2,%3}, {%4,%5,%6,%7}, {%8,%9}, {%0,%1,%2,%3};"
                 : "+f"(c[0]), "+f"(c[1]), "+f"(c[2]), "+f"(c[3])
                 : "r"(a0), "r"(a1), "r"(a2), "r"(a3), "r"(b0), "r"(b1));
}
__device__ __forceinline__ float ex2f(float x) {
    float y; asm("ex2.approx.f32 %0, %1;" : "=f"(y) : "f"(x)); return y;
}
__device__ __forceinline__ uint32_t packh(float x, float y) {
    __half2 t = __floats2half2_rn(x, y);
    return *(uint32_t*)&t;
}
// fp16 hi/lo split of a pair
__device__ __forceinline__ void hilo2h(float v0, float v1, uint32_t& hw, uint32_t& lw) {
    __half h0 = __float2half_rn(v0), h1 = __float2half_rn(v1);
    __half2 hp = {h0, h1};
    hw = *(uint32_t*)&hp;
    __half2 lp = __floats2half2_rn(v0 - __half2float(h0), v1 - __half2float(h1));
    lw = *(uint32_t*)&lp;
}

// ---------------------------------------------------------------------------
// Fused fp32 -> fp16 convert for x + 4 weight matrices (one kernel)
// ---------------------------------------------------------------------------
#define XN4 (BS*DD/4)      // 2097152
#define WN4 (DD*DD/4)      // 262144

__global__ __launch_bounds__(256)
void cvt_all_kernel(const float* __restrict__ x,
                    const float* __restrict__ wq, const float* __restrict__ wk,
                    const float* __restrict__ wv, const float* __restrict__ wo)
{
    int i = blockIdx.x * 256 + threadIdx.x;
    const float* src;
    __half* dst;
    int off;
    if (i < XN4)                { src = x;  dst = g_x16;            off = i; }
    else if (i < XN4 + WN4)     { src = wq; dst = g_w16;            off = i - XN4; }
    else if (i < XN4 + 2*WN4)   { src = wk; dst = g_w16 + DD*DD;    off = i - XN4 - WN4; }
    else if (i < XN4 + 3*WN4)   { src = wv; dst = g_w16 + 2*DD*DD;  off = i - XN4 - 2*WN4; }
    else if (i < XN4 + 4*WN4)   { src = wo; dst = g_wo16;           off = i - XN4 - 3*WN4; }
    else return;
    float4 v = ((const float4*)src)[off];
    ((uint32_t*)dst)[off*2+0] = packh(v.x, v.y);
    ((uint32_t*)dst)[off*2+1] = packh(v.z, v.w);
}

// ---------------------------------------------------------------------------
// fp16 single-pass GEMM via mma.sync: C = A * B^T.
// CTA 128x256, BK=32, 4-stage cp.async, 8 warps (2M x 4N), warp 64x64.
// mode 0: write Q fp16 hi/lo (scaled 0.125*log2e) / K fp16 / V fp16
// mode 1: fp32 out + bias
// ---------------------------------------------------------------------------
#define GM_BM 128
#define GM_BN 256
#define GM_BK 32
#define GM_TILES 32            // K=1024 / 32
#define LSTR 40                // smem row stride in halves (80B)

#define TEN_A  10240u          // 128x32 fp16 tensor (LSTR-padded)
#define STG_B  30720u          // A + B per stage
#define GSMEM  122880          // 4 stages

#define QSCALE 0.18033688011112042f   // (1/8) * log2(e)

__global__ __launch_bounds__(256, 1)
void gemm_fp16_kernel(const __half* __restrict__ Aa,
                      const __half* __restrict__ Bw,
                      float* __restrict__ outp,
                      const float* __restrict__ bias,
                      int mode)
{
    extern __shared__ char smem[];
    const uint32_t sb = smem_u32(smem);

    const int tid = threadIdx.x;
    const int lid = tid & 31;
    const int wid = tid >> 5;
    const int wm = wid >> 2;      // 0..1 (64 rows)
    const int wn = wid & 3;       // 0..3 (64 cols)

    const int m0 = blockIdx.x * GM_BM;
    const int n0 = blockIdx.y * GM_BN;

    float acc[4][8][4];
    #pragma unroll
    for (int i = 0; i < 4; i++)
        #pragma unroll
        for (int j = 0; j < 8; j++)
            #pragma unroll
            for (int c = 0; c < 4; c++) acc[i][j][c] = 0.f;

    auto load_tile = [&](int t) {
        const int k0 = t * GM_BK;
        const uint32_t base = sb + (uint32_t)(t & 3) * STG_B;
        #pragma unroll
        for (int it = 0; it < 2; it++) {
            int idx = tid + it * 256;  int r = idx >> 2, c = idx & 3;
            cp16(base + (uint32_t)(r * LSTR + c * 8) * 2,
                 Aa + (size_t)(m0 + r) * DD + k0 + c * 8);
        }
        #pragma unroll
        for (int it = 0; it < 4; it++) {
            int idx = tid + it * 256;  int r = idx >> 2, c = idx & 3;
            cp16(base + TEN_A + (uint32_t)(r * LSTR + c * 8) * 2,
                 Bw + (size_t)(n0 + r) * DD + k0 + c * 8);
        }
        CP_COMMIT();
    };

    load_tile(0);
    load_tile(1);
    load_tile(2);

    const int q = lid >> 3;
    const int r = lid & 7;
    const int arow = r + (q & 1) * 8;
    const int acol = (q >> 1) * 8;
    const int brow = r + (q >> 1) * 8;
    const int bcol = (q & 1) * 8;

    for (int i = 0; i < GM_TILES; i++) {
        if (i + 2 < GM_TILES) { CP_WAIT2(); }
        else if (i + 1 < GM_TILES) { CP_WAIT1(); }
        else { CP_WAIT0(); }
        __syncthreads();
        if (i + 3 < GM_TILES) load_tile(i + 3);

        const uint32_t stg = sb + (uint32_t)(i & 3) * STG_B;

        #pragma unroll
        for (int kst = 0; kst < 2; kst++) {
            const int kb = kst * 16;
            uint32_t b[8][2];
            #pragma unroll
            for (int np = 0; np < 4; np++) {
                uint32_t addr = stg + TEN_A +
                    (uint32_t)((wn * 64 + np * 16 + brow) * LSTR + kb + bcol) * 2;
                ldsm4(b[2*np][0], b[2*np][1], b[2*np+1][0], b[2*np+1][1], addr);
            }
            uint32_t a[4][4];
            #pragma unroll
            for (int mt = 0; mt < 4; mt++) {
                uint32_t addr = stg +
                    (uint32_t)((wm * 64 + mt * 16 + arow) * LSTR + kb + acol) * 2;
                ldsm4(a[mt][0], a[mt][1], a[mt][2], a[mt][3], addr);
            }
            #pragma unroll
            for (int mt = 0; mt < 4; mt++)
                #pragma unroll
                for (int nt = 0; nt < 8; nt++)
                    mma16816h(acc[mt][nt], a[mt][0], a[mt][1], a[mt][2], a[mt][3],
                              b[nt][0], b[nt][1]);
        }
    }

    // Epilogue
    if (mode == 0) {
        const int sel = n0 >> 10;
        const int ncta = n0 & (DD - 1);
        #pragma unroll
        for (int mt = 0; mt < 4; mt++) {
            int row = m0 + wm * 64 + mt * 16 + (lid >> 2);
            #pragma unroll
            for (int nt = 0; nt < 8; nt++) {
                int col = ncta + wn * 64 + nt * 8 + (lid & 3) * 2;
                if (sel == 0) {
                    uint32_t hw, lw;
                    hilo2h(acc[mt][nt][0] * QSCALE, acc[mt][nt][1] * QSCALE, hw, lw);
                    *(uint32_t*)&g_q16h[(size_t)row * DD + col] = hw;
                    *(uint32_t*)&g_q16l[(size_t)row * DD + col] = lw;
                    hilo2h(acc[mt][nt][2] * QSCALE, acc[mt][nt][3] * QSCALE, hw, lw);
                    *(uint32_t*)&g_q16h[(size_t)(row + 8) * DD + col] = hw;
                    *(uint32_t*)&g_q16l[(size_t)(row + 8) * DD + col] = lw;
                } else {
                    __half* __restrict__ op = (sel == 1) ? g_k16 : g_v16;
                    *(uint32_t*)&op[(size_t)row * DD + col] =
                        packh(acc[mt][nt][0], acc[mt][nt][1]);
                    *(uint32_t*)&op[(size_t)(row + 8) * DD + col] =
                        packh(acc[mt][nt][2], acc[mt][nt][3]);
                }
            }
        }
    } else {
        #pragma unroll
        for (int mt = 0; mt < 4; mt++) {
            int row = m0 + wm * 64 + mt * 16 + (lid >> 2);
            #pragma unroll
            for (int nt = 0; nt < 8; nt++) {
                int col = n0 + wn * 64 + nt * 8 + (lid & 3) * 2;
                float2 bb = *(const float2*)&bias[col];
                float2 v0 = {acc[mt][nt][0] + bb.x, acc[mt][nt][1] + bb.y};
                float2 v1 = {acc[mt][nt][2] + bb.x, acc[mt][nt][3] + bb.y};
                *(float2*)&outp[(size_t)row * DD + col] = v0;
                *(float2*)&outp[(size_t)(row + 8) * DD + col] = v1;
            }
        }
    }
}

// ---------------------------------------------------------------------------
// Flash attention (causal), fp16 MMA.
// S = (Qh + Ql) K^T  (Q fp16 hi/lo, K fp16 single, 2 passes)
// O = P V            (both fp16 single, 1 pass)
// CTA: 128 q-rows (8 warps x 16), k-tiles of 64, cp.async double-buffered.
// Scores in log2 domain (Q pre-scaled by 0.125*log2e) -> ex2 softmax.
// ---------------------------------------------------------------------------
#define BR 128
#define BC 64
#define KSTR 72                 // padded fp16 stride (144B rows)

#define FQ_OFF  0u              // Q hi/lo: 2 * 128*72*2 = 36864
#define FST_OFF 36864u          // stages: 2 * 18432
#define FSTAGE  18432u          // per stage: K +0, V +9216
#define FTEN    9216u
#define FSMEM   73728

__global__ __launch_bounds__(256)
void flash_mma_kernel()
{
    extern __shared__ char smem[];
    const uint32_t sb = smem_u32(smem);

    const int tid = threadIdx.x;
    const int lid = tid & 31;
    const int wid = tid >> 5;
    const int itile = blockIdx.x;
    const int bh = blockIdx.y;
    const int b = bh >> 4, h = bh & 15;
    const int qbase = itile * BR;
    const int nkt = 2 * itile + 2;

    const size_t gq  = ((size_t)(b * SS + qbase)) * DD + h * HD;
    const size_t gkv = ((size_t)(b * SS)) * DD + h * HD;

    // Q hi/lo -> smem
    #pragma unroll
    for (int t = 0; t < 8; t++) {
        int idx = tid + t * 256;            // 0..2047
        int ten = idx >> 10;                // 0 = hi, 1 = lo
        int r = (idx >> 3) & 127;
        int c = idx & 7;
        const __half* src = ten ? g_q16l : g_q16h;
        cp16(sb + FQ_OFF + (uint32_t)ten * (BR * KSTR * 2) + (uint32_t)(r * KSTR + c * 8) * 2,
             src + gq + (size_t)r * DD + c * 8);
    }
    CP_COMMIT();

    auto load_kv = [&](int kt) {
        const int buf = kt & 1;
        const uint32_t base = sb + FST_OFF + buf * FSTAGE;
        const size_t gk = gkv + (size_t)(kt * BC) * DD;
        #pragma unroll
        for (int t = 0; t < 4; t++) {
            int idx = tid + t * 256;        // 0..1023
            int ten = idx >> 9;             // 0 = K, 1 = V
            int r = (idx >> 3) & 63;
            int c = idx & 7;
            const __half* src = ten ? g_v16 : g_k16;
            cp16(base + (uint32_t)ten * FTEN + (uint32_t)(r * KSTR + c * 8) * 2,
                 src + gk + (size_t)r * DD + c * 8);
        }
        CP_COMMIT();
    };

    load_kv(0);
    if (nkt > 1) load_kv(1);

    CP_WAIT2();                 // Q group done
    __syncthreads();

    const int q4 = lid >> 3;
    const int r8 = lid & 7;
    const int arow = r8 + (q4 & 1) * 8;
    const int acol = (q4 >> 1) * 8;
    const int brow = r8 + (q4 >> 1) * 8;
    const int bcol = (q4 & 1) * 8;

    uint32_t qh[4][4], ql[4][4];
    #pragma unroll
    for (int ks = 0; ks < 4; ks++) {
        uint32_t ao = (uint32_t)((wid * 16 + arow) * KSTR + ks * 16 + acol) * 2;
        ldsm4(qh[ks][0], qh[ks][1], qh[ks][2], qh[ks][3], sb + FQ_OFF + ao);
        ldsm4(ql[ks][0], ql[ks][1], ql[ks][2], ql[ks][3], sb + FQ_OFF + BR * KSTR * 2 + ao);
    }

    float o[8][4];
    #pragma unroll
    for (int nf = 0; nf < 8; nf++)
        #pragma unroll
        for (int c = 0; c < 4; c++) o[nf][c] = 0.f;
    float m0 = -1e30f, m1 = -1e30f, ls0 = 0.f, ls1 = 0.f;

    const int rowg = qbase + wid * 16 + (lid >> 2);

    for (int kt = 0; kt < nkt; kt++) {
        const int buf = kt & 1;
        if (kt + 1 < nkt) { CP_WAIT1(); } else { CP_WAIT0(); }
        __syncthreads();

        const uint32_t kb = sb + FST_OFF + buf * FSTAGE;

        // ---- S = (Qh + Ql) K^T ----
        float s[8][4];
        #pragma unroll
        for (int nf = 0; nf < 8; nf++)
            #pragma unroll
            for (int c = 0; c < 4; c++) s[nf][c] = 0.f;

        #pragma unroll
        for (int ks = 0; ks < 4; ks++) {
            #pragma unroll
            for (int np = 0; np < 4; np++) {
                uint32_t ao = (uint32_t)((np * 16 + brow) * KSTR + ks * 16 + bcol) * 2;
                uint32_t k0, k1, k2, k3;
                ldsm4(k0, k1, k2, k3, kb + ao);
                mma16816h(s[2*np],   qh[ks][0], qh[ks][1], qh[ks][2], qh[ks][3], k0, k1);
                mma16816h(s[2*np+1], qh[ks][0], qh[ks][1], qh[ks][2], qh[ks][3], k2, k3);
                mma16816h(s[2*np],   ql[ks][0], ql[ks][1], ql[ks][2], ql[ks][3], k0, k1);
                mma16816h(s[2*np+1], ql[ks][0], ql[ks][1], ql[ks][2], ql[ks][3], k2, k3);
            }
        }

        // ---- causal mask on the last two k-tiles ----
        if (kt >= nkt - 2) {
            const int colb = kt * BC + (lid & 3) * 2;
            #pragma unroll
            for (int nf = 0; nf < 8; nf++) {
                int c0 = colb + nf * 8;
                if (c0     > rowg)     s[nf][0] = -1e30f;
                if (c0 + 1 > rowg)     s[nf][1] = -1e30f;
                if (c0     > rowg + 8) s[nf][2] = -1e30f;
                if (c0 + 1 > rowg + 8) s[nf][3] = -1e30f;
            }
        }

        // ---- online softmax (log2 domain) ----
        float mx0 = -1e30f, mx1 = -1e30f;
        #pragma unroll
        for (int nf = 0; nf < 8; nf++) {
            mx0 = fmaxf(mx0, fmaxf(s[nf][0], s[nf][1]));
            mx1 = fmaxf(mx1, fmaxf(s[nf][2], s[nf][3]));
        }
        mx0 = fmaxf(mx0, __shfl_xor_sync(0xffffffffu, mx0, 1));
        mx0 = fmaxf(mx0, __shfl_xor_sync(0xffffffffu, mx0, 2));
        mx1 = fmaxf(mx1, __shfl_xor_sync(0xffffffffu, mx1, 1));
        mx1 = fmaxf(mx1, __shfl_xor_sync(0xffffffffu, mx1, 2));
        const float nm0 = fmaxf(m0, mx0), nm1 = fmaxf(m1, mx1);
        const float al0 = ex2f(m0 - nm0), al1 = ex2f(m1 - nm1);
        m0 = nm0; m1 = nm1;
        ls0 *= al0; ls1 *= al1;

        #pragma unroll
        for (int nf = 0; nf < 8; nf++) {
            s[nf][0] = ex2f(s[nf][0] - m0);
            s[nf][1] = ex2f(s[nf][1] - m0);
            s[nf][2] = ex2f(s[nf][2] - m1);
            s[nf][3] = ex2f(s[nf][3] - m1);
            ls0 += s[nf][0] + s[nf][1];
            ls1 += s[nf][2] + s[nf][3];
        }
        #pragma unroll
        for (int nf = 0; nf < 8; nf++) {
            o[nf][0] *= al0; o[nf][1] *= al0;
            o[nf][2] *= al1; o[nf][3] *= al1;
        }

        // ---- O += P V (fp16 single pass) ----
        const int vlane_r = lid & 15;
        const int vlane_c = (lid >> 4) * 8;
        #pragma unroll
        for (int ks = 0; ks < 4; ks++) {
            uint32_t pa[4];
            pa[0] = packh(s[2*ks][0],   s[2*ks][1]);
            pa[1] = packh(s[2*ks][2],   s[2*ks][3]);
            pa[2] = packh(s[2*ks+1][0], s[2*ks+1][1]);
            pa[3] = packh(s[2*ks+1][2], s[2*ks+1][3]);
            #pragma unroll
            for (int np = 0; np < 4; np++) {
                uint32_t ao = (uint32_t)((ks * 16 + vlane_r) * KSTR + np * 16 + vlane_c) * 2;
                uint32_t v0, v1, v2, v3;
                ldsm4t(v0, v1, v2, v3, kb + FTEN + ao);
                mma16816h(o[2*np],   pa[0], pa[1], pa[2], pa[3], v0, v1);
                mma16816h(o[2*np+1], pa[0], pa[1], pa[2], pa[3], v2, v3);
            }
        }

        __syncthreads();
        if (kt + 2 < nkt) load_kv(kt + 2);
    }

    // ---- epilogue: normalize, write ctx fp16 ----
    ls0 += __shfl_xor_sync(0xffffffffu, ls0, 1);
    ls0 += __shfl_xor_sync(0xffffffffu, ls0, 2);
    ls1 += __shfl_xor_sync(0xffffffffu, ls1, 1);
    ls1 += __shfl_xor_sync(0xffffffffu, ls1, 2);
    const float li0 = 1.0f / ls0, li1 = 1.0f / ls1;

    const size_t row0 = (size_t)(b * SS + rowg);
    const int colb = h * HD + (lid & 3) * 2;
    #pragma unroll
    for (int nf = 0; nf < 8; nf++) {
        int col = colb + nf * 8;
        *(uint32_t*)&g_c16[row0 * DD + col]       = packh(o[nf][0] * li0, o[nf][1] * li0);
        *(uint32_t*)&g_c16[(row0 + 8) * DD + col] = packh(o[nf][2] * li1, o[nf][3] * li1);
    }
}

// ---------------------------------------------------------------------------

extern "C" void kernel_launch(void* const* d_in, const int* in_sizes, int n_in,
                              void* d_out, int out_size)
{
    const float* x    = (const float*)d_in[0];
    const float* wq   = (const float*)d_in[1];
    const float* wk   = (const float*)d_in[2];
    const float* wv   = (const float*)d_in[3];
    const float* wo   = (const float*)d_in[4];
    const float* wo_b = (const float*)d_in[5];
    float* out = (float*)d_out;

    static int attr_done = 0;
    if (!attr_done) {
        cudaFuncSetAttribute(flash_mma_kernel,
                             cudaFuncAttributeMaxDynamicSharedMemorySize, FSMEM);
        cudaFuncSetAttribute(gemm_fp16_kernel,
                             cudaFuncAttributeMaxDynamicSharedMemorySize, GSMEM);
        attr_done = 1;
    }

    __half *x16, *w16, *wo16, *c16;
    cudaGetSymbolAddress((void**)&x16,  g_x16);
    cudaGetSymbolAddress((void**)&w16,  g_w16);
    cudaGetSymbolAddress((void**)&wo16, g_wo16);
    cudaGetSymbolAddress((void**)&c16,  g_c16);

    // 1. convert x + all weights to fp16 (single fused kernel)
    const int cvt_total = XN4 + 4 * WN4;
    cvt_all_kernel<<<(cvt_total + 255)/256, 256>>>(x, wq, wk, wv, wo);

    // 2. fused QKV projection (fp16 1-pass) -> Q fp16 hi/lo, K/V fp16
    gemm_fp16_kernel<<<dim3(BS/GM_BM, 3*DD/GM_BN), 256, GSMEM>>>(
        x16, w16, nullptr, nullptr, 0);

    // 3. causal flash attention (fp16, S 2-pass / PV 1-pass) -> ctx fp16
    flash_mma_kernel<<<dim3(SS/BR, BB*HH), 256, FSMEM>>>();

    // 4. output projection + bias (fp16 1-pass, fp32 out)
    gemm_fp16_kernel<<<dim3(BS/GM_BM, DD/GM_BN), 256, GSMEM>>>(
        c16, wo16, out, wo_b, 1);
}